// round 1
// baseline (speedup 1.0000x reference)
#include <cuda_runtime.h>

// Fixed problem shape (VectorQuantizerRestart): z [16,128,4096] fp32, codebook [1024,128] fp32
#define D_DIM    128
#define T_DIM    4096
#define K_DIM    1024
#define N_TOK    65536
#define TOK_TILE 64
#define KCHUNK   64
#define CPAD     68     // pad 64 -> 68 floats: transposed store step 68 % 32 = 4 (mild), float4-aligned reads

__device__ float g_cnorm[K_DIM];
__device__ int   g_idx[N_TOK];

// Packed dual-FMA: fma.rn.f32x2 (sm_100+). Restores full 128 FMA-lane/cyc/SM rate
// (3-reg FFMA is half-rate rt_SMSP=2 per B300 measurements).
__device__ __forceinline__ void ffma2(float2& d, const float2 a, const float2 b) {
    unsigned long long dd, aa, bb;
    dd = *reinterpret_cast<const unsigned long long*>(&d);
    aa = *reinterpret_cast<const unsigned long long*>(&a);
    bb = *reinterpret_cast<const unsigned long long*>(&b);
    asm("fma.rn.f32x2 %0, %1, %2, %0;" : "+l"(dd) : "l"(aa), "l"(bb));
    d = *reinterpret_cast<float2*>(&dd);
}

// ---------------------------------------------------------------------------
// Kernel 1: codebook squared norms. One warp per code row, coalesced reads.
// ---------------------------------------------------------------------------
__global__ void vq_cnorm_kernel(const float* __restrict__ cb) {
    int w    = (blockIdx.x * blockDim.x + threadIdx.x) >> 5;
    int lane = threadIdx.x & 31;
    if (w >= K_DIM) return;
    float s = 0.f;
    #pragma unroll
    for (int d = lane; d < D_DIM; d += 32) {
        float v = cb[(size_t)w * D_DIM + d];
        s = fmaf(v, v, s);
    }
    #pragma unroll
    for (int o = 16; o > 0; o >>= 1) s += __shfl_xor_sync(0xffffffffu, s, o);
    if (lane == 0) g_cnorm[w] = s;
}

// ---------------------------------------------------------------------------
// Kernel 2: argmin_k ( ||c_k||^2 - 2 * z_n . c_k ).  (||z||^2 shifts all k equally.)
// Block = 256 threads (16 tx codes x 16 ty tokens), tile = 64 tokens x 64 codes/chunk,
// 16 chunks over K=1024. 4x4 micro-tile per thread via packed f32x2 FMAs.
// ---------------------------------------------------------------------------
__global__ __launch_bounds__(256) void vq_argmin_kernel(const float* __restrict__ z,
                                                        const float* __restrict__ cb) {
    extern __shared__ float sm[];
    float* zs = sm;                          // [D][TOK_TILE]  32 KB
    float* cs = sm + D_DIM * TOK_TILE;       // [D][CPAD]      34.8 KB (transposed codebook chunk)
    float* cn = cs + D_DIM * CPAD;           // [KCHUNK]

    const int tid = threadIdx.x;
    const int tx  = tid & 15;                // code group
    const int ty  = tid >> 4;                // token group
    const int n0  = blockIdx.x * TOK_TILE;   // first token (tile never crosses batch: 4096 % 64 == 0)
    const int b   = n0 >> 12;                // / T_DIM
    const int t0  = n0 & (T_DIM - 1);

    // Load z tile: z[b, d, t0..t0+63] -> zs[d][t'] (coalesced 256B rows)
    const float* zb = z + (size_t)b * D_DIM * T_DIM + t0;
    for (int i = tid; i < D_DIM * TOK_TILE; i += 256) {
        int d = i >> 6, tt = i & 63;
        zs[i] = zb[(size_t)d * T_DIM + tt];
    }

    float minv[4];
    int   mini[4];
    #pragma unroll
    for (int j = 0; j < 4; j++) { minv[j] = 3.4e38f; mini[j] = 0; }

    for (int kc = 0; kc < K_DIM; kc += KCHUNK) {
        __syncthreads();   // prev-chunk compute done (and zs visible on first iter)
        // Load codebook chunk transposed: cb[kc+kk][d] -> cs[d][kk]
        for (int i = tid; i < KCHUNK * D_DIM; i += 256) {
            int kk = i >> 7, d = i & 127;
            cs[d * CPAD + kk] = cb[(size_t)(kc + kk) * D_DIM + d];
        }
        if (tid < KCHUNK) cn[tid] = g_cnorm[kc + tid];
        __syncthreads();

        float2 acc[2][4];
        #pragma unroll
        for (int p = 0; p < 2; p++)
            #pragma unroll
            for (int q = 0; q < 4; q++) acc[p][q] = make_float2(0.f, 0.f);

        const float* zp = zs + ty * 4;
        const float* cp = cs + tx * 4;
        #pragma unroll 16
        for (int d = 0; d < D_DIM; ++d) {
            float4 av = *reinterpret_cast<const float4*>(zp + d * TOK_TILE);
            float4 bv = *reinterpret_cast<const float4*>(cp + d * CPAD);
            float2 a0 = make_float2(av.x, av.y);   // tokens ty*4+0, +1
            float2 a1 = make_float2(av.z, av.w);   // tokens ty*4+2, +3
            float  bq0 = bv.x, bq1 = bv.y, bq2 = bv.z, bq3 = bv.w;
            float2 b2;
            b2 = make_float2(bq0, bq0); ffma2(acc[0][0], a0, b2); ffma2(acc[1][0], a1, b2);
            b2 = make_float2(bq1, bq1); ffma2(acc[0][1], a0, b2); ffma2(acc[1][1], a1, b2);
            b2 = make_float2(bq2, bq2); ffma2(acc[0][2], a0, b2); ffma2(acc[1][2], a1, b2);
            b2 = make_float2(bq3, bq3); ffma2(acc[0][3], a0, b2); ffma2(acc[1][3], a1, b2);
        }

        // dist = ||c||^2 - 2*dot ; update running min (k ascends within thread -> strict < keeps lowest idx)
        #pragma unroll
        for (int q = 0; q < 4; q++) {
            int   k = kc + tx * 4 + q;
            float c = cn[tx * 4 + q];
            #pragma unroll
            for (int p = 0; p < 2; p++) {
                float d0 = fmaf(-2.f, acc[p][q].x, c);
                float d1 = fmaf(-2.f, acc[p][q].y, c);
                int j0 = 2 * p, j1 = 2 * p + 1;
                if (d0 < minv[j0] || (d0 == minv[j0] && k < mini[j0])) { minv[j0] = d0; mini[j0] = k; }
                if (d1 < minv[j1] || (d1 == minv[j1] && k < mini[j1])) { minv[j1] = d1; mini[j1] = k; }
            }
        }
    }

    // Cross-thread reduce over the 16 tx threads per token row (reuse smem).
    __syncthreads();
    float* rv = sm;                                       // [64][16]
    int*   ri = reinterpret_cast<int*>(sm + TOK_TILE * 16);
    #pragma unroll
    for (int j = 0; j < 4; j++) {
        int tok = ty * 4 + j;
        rv[tok * 16 + tx] = minv[j];
        ri[tok * 16 + tx] = mini[j];
    }
    __syncthreads();
    if (tid < TOK_TILE) {
        float bv = rv[tid * 16];
        int   bi = ri[tid * 16];
        #pragma unroll
        for (int x = 1; x < 16; x++) {
            float v = rv[tid * 16 + x];
            int   k = ri[tid * 16 + x];
            if (v < bv || (v == bv && k < bi)) { bv = v; bi = k; }
        }
        g_idx[n0 + tid] = bi;
    }
}

// ---------------------------------------------------------------------------
// Kernel 3: gather. out[b, d, t] = cb[idx[b*T+t], d]. Coalesced on out & idx;
// codebook (512 KB) stays L2-resident for the scattered reads.
// ---------------------------------------------------------------------------
__global__ void vq_gather_kernel(const float* __restrict__ cb, float* __restrict__ out) {
    int gid = blockIdx.x * blockDim.x + threadIdx.x;      // < 8.4M, fits int
    int t = gid & (T_DIM - 1);
    int r = gid >> 12;            // b*128 + d
    int d = r & 127;
    int b = r >> 7;
    int idx = g_idx[b * T_DIM + t];
    out[gid] = __ldg(cb + (size_t)idx * D_DIM + d);
}

// ---------------------------------------------------------------------------
extern "C" void kernel_launch(void* const* d_in, const int* in_sizes, int n_in,
                              void* d_out, int out_size) {
    const float* z  = (const float*)d_in[0];
    const float* cb = (const float*)d_in[1];
    float* out = (float*)d_out;

    const int smem = (D_DIM * TOK_TILE + D_DIM * CPAD + KCHUNK) * 4;  // 67840 B
    cudaFuncSetAttribute(vq_argmin_kernel, cudaFuncAttributeMaxDynamicSharedMemorySize, smem);

    vq_cnorm_kernel<<<K_DIM / 8, 256>>>(cb);                 // 8 warps/block, warp per code
    vq_argmin_kernel<<<N_TOK / TOK_TILE, 256, smem>>>(z, cb);
    vq_gather_kernel<<<(N_TOK * D_DIM) / 256, 256>>>(cb, out);
}

// round 2
// speedup vs baseline: 1.3695x; 1.3695x over previous
#include <cuda_runtime.h>

// VectorQuantizerRestart: z [16,128,4096] fp32, codebook [1024,128] fp32
#define D_DIM    128
#define T_DIM    4096
#define K_DIM    1024
#define N_TOK    65536
#define TOK_TILE 128
#define KCHUNK   64
#define CPAD     68     // transposed codebook pad: 4-way store conflict, 16B-aligned reads

__device__ float g_cnorm[K_DIM];
__device__ int   g_idx[N_TOK];

// Packed dual-FMA (sm_100+): full 128 MAC-lane/cyc/SM rate vs half-rate 3-reg FFMA.
__device__ __forceinline__ void ffma2(float2& d, const float2 a, const float2 b) {
    unsigned long long dd, aa, bb;
    dd = *reinterpret_cast<const unsigned long long*>(&d);
    aa = *reinterpret_cast<const unsigned long long*>(&a);
    bb = *reinterpret_cast<const unsigned long long*>(&b);
    asm("fma.rn.f32x2 %0, %1, %2, %0;" : "+l"(dd) : "l"(aa), "l"(bb));
    d = *reinterpret_cast<float2*>(&dd);
}

// ---------------------------------------------------------------------------
// Kernel 1: codebook squared norms (one warp per code).
// ---------------------------------------------------------------------------
__global__ void vq_cnorm_kernel(const float* __restrict__ cb) {
    int w    = (blockIdx.x * blockDim.x + threadIdx.x) >> 5;
    int lane = threadIdx.x & 31;
    if (w >= K_DIM) return;
    float s = 0.f;
    #pragma unroll
    for (int d = lane; d < D_DIM; d += 32) {
        float v = cb[(size_t)w * D_DIM + d];
        s = fmaf(v, v, s);
    }
    #pragma unroll
    for (int o = 16; o > 0; o >>= 1) s += __shfl_xor_sync(0xffffffffu, s, o);
    if (lane == 0) g_cnorm[w] = s;
}

// ---------------------------------------------------------------------------
// Kernel 2: argmin_k ( ||c_k||^2 - 2 z.c ). Block 256 = 16tx(codes) x 16ty(tokens),
// tile = 128 tokens x 64-code chunks, micro-tile 8 tokens x 4 codes per thread.
// Warp = {2 ty} x {16 tx}: token LDS is 2-distinct (broadcast-cheap), FMA pipe binds.
// ---------------------------------------------------------------------------
__global__ __launch_bounds__(256) void vq_argmin_kernel(const float* __restrict__ z,
                                                        const float* __restrict__ cb) {
    extern __shared__ float sm[];
    float* zs = sm;                           // [D][TOK_TILE]  64 KB
    float* cs = sm + D_DIM * TOK_TILE;        // [D][CPAD]      34.8 KB
    float* cn = cs + D_DIM * CPAD;            // [KCHUNK]

    const int tid = threadIdx.x;
    const int tx  = tid & 15;                 // code group  (4 codes)
    const int ty  = tid >> 4;                 // token group (8 tokens)
    const int n0  = blockIdx.x * TOK_TILE;    // 4096 % 128 == 0: never crosses batch
    const int b   = n0 >> 12;
    const int t0  = n0 & (T_DIM - 1);

    // z tile: z[b, d, t0..t0+127] -> zs[d][t'] (coalesced 512B rows, conflict-free stores)
    const float* zb = z + (size_t)b * D_DIM * T_DIM + t0;
    #pragma unroll
    for (int i = tid; i < D_DIM * TOK_TILE; i += 256) {
        int d = i >> 7, tt = i & 127;
        zs[i] = zb[(size_t)d * T_DIM + tt];
    }

    float minv[8];
    int   mini[8];
    #pragma unroll
    for (int j = 0; j < 8; j++) { minv[j] = 3.4e38f; mini[j] = 0; }

    for (int kc = 0; kc < K_DIM; kc += KCHUNK) {
        __syncthreads();
        // codebook chunk transposed: cb[kc+kk][d] -> cs[d][kk] (gmem-coalesced)
        #pragma unroll
        for (int i = tid; i < KCHUNK * D_DIM; i += 256) {
            int kk = i >> 7, d = i & 127;
            cs[d * CPAD + kk] = cb[(size_t)(kc + kk) * D_DIM + d];
        }
        if (tid < KCHUNK) cn[tid] = g_cnorm[kc + tid];
        __syncthreads();

        float2 acc[4][4];                     // [token-pair][code]
        #pragma unroll
        for (int p = 0; p < 4; p++)
            #pragma unroll
            for (int q = 0; q < 4; q++) acc[p][q] = make_float2(0.f, 0.f);

        const float* zp = zs + ty * 8;
        const float* cp = cs + tx * 4;
        #pragma unroll 8
        for (int d = 0; d < D_DIM; ++d) {
            float4 av0 = *reinterpret_cast<const float4*>(zp + d * TOK_TILE);
            float4 av1 = *reinterpret_cast<const float4*>(zp + d * TOK_TILE + 4);
            float4 bv  = *reinterpret_cast<const float4*>(cp + d * CPAD);
            float2 a0 = make_float2(av0.x, av0.y);
            float2 a1 = make_float2(av0.z, av0.w);
            float2 a2 = make_float2(av1.x, av1.y);
            float2 a3 = make_float2(av1.z, av1.w);
            float2 b2;
            b2 = make_float2(bv.x, bv.x);
            ffma2(acc[0][0], a0, b2); ffma2(acc[1][0], a1, b2);
            ffma2(acc[2][0], a2, b2); ffma2(acc[3][0], a3, b2);
            b2 = make_float2(bv.y, bv.y);
            ffma2(acc[0][1], a0, b2); ffma2(acc[1][1], a1, b2);
            ffma2(acc[2][1], a2, b2); ffma2(acc[3][1], a3, b2);
            b2 = make_float2(bv.z, bv.z);
            ffma2(acc[0][2], a0, b2); ffma2(acc[1][2], a1, b2);
            ffma2(acc[2][2], a2, b2); ffma2(acc[3][2], a3, b2);
            b2 = make_float2(bv.w, bv.w);
            ffma2(acc[0][3], a0, b2); ffma2(acc[1][3], a1, b2);
            ffma2(acc[2][3], a2, b2); ffma2(acc[3][3], a3, b2);
        }

        // dist = ||c||^2 - 2*dot; k ascends within thread -> strict < keeps lowest idx
        #pragma unroll
        for (int q = 0; q < 4; q++) {
            int   k = kc + tx * 4 + q;
            float c = cn[tx * 4 + q];
            #pragma unroll
            for (int p = 0; p < 4; p++) {
                float d0 = fmaf(-2.f, acc[p][q].x, c);
                float d1 = fmaf(-2.f, acc[p][q].y, c);
                int j0 = 2 * p, j1 = 2 * p + 1;
                if (d0 < minv[j0] || (d0 == minv[j0] && k < mini[j0])) { minv[j0] = d0; mini[j0] = k; }
                if (d1 < minv[j1] || (d1 == minv[j1] && k < mini[j1])) { minv[j1] = d1; mini[j1] = k; }
            }
        }
    }

    // Cross-thread reduce over the 16 tx candidates per token.
    __syncthreads();
    float* rv = sm;                                        // [128][16] floats
    int*   ri = reinterpret_cast<int*>(sm + TOK_TILE * 16);
    #pragma unroll
    for (int j = 0; j < 8; j++) {
        int tok = ty * 8 + j;
        rv[tok * 16 + tx] = minv[j];
        ri[tok * 16 + tx] = mini[j];
    }
    __syncthreads();
    if (tid < TOK_TILE) {
        float bv = rv[tid * 16];
        int   bi = ri[tid * 16];
        #pragma unroll
        for (int x = 1; x < 16; x++) {
            float v = rv[tid * 16 + x];
            int   k = ri[tid * 16 + x];
            if (v < bv || (v == bv && k < bi)) { bv = v; bi = k; }
        }
        g_idx[n0 + tid] = bi;
    }
}

// ---------------------------------------------------------------------------
// Kernel 3: gather. Each thread: 4 consecutive t -> float4 store (coalesced),
// 4 scattered 4B codebook reads (cb is 512KB, L2-resident).
// ---------------------------------------------------------------------------
__global__ void vq_gather_kernel(const float* __restrict__ cb, float* __restrict__ out) {
    int gid = blockIdx.x * blockDim.x + threadIdx.x;   // over N_TOK*D/4
    int t4 = gid & (T_DIM / 4 - 1);                    // t/4
    int r  = gid >> 10;                                // b*128 + d
    int d  = r & 127;
    int b  = r >> 7;
    const int* ip = g_idx + b * T_DIM + t4 * 4;
    float4 o;
    o.x = __ldg(cb + (size_t)ip[0] * D_DIM + d);
    o.y = __ldg(cb + (size_t)ip[1] * D_DIM + d);
    o.z = __ldg(cb + (size_t)ip[2] * D_DIM + d);
    o.w = __ldg(cb + (size_t)ip[3] * D_DIM + d);
    reinterpret_cast<float4*>(out)[gid] = o;
}

// ---------------------------------------------------------------------------
extern "C" void kernel_launch(void* const* d_in, const int* in_sizes, int n_in,
                              void* d_out, int out_size) {
    const float* z  = (const float*)d_in[0];
    const float* cb = (const float*)d_in[1];
    float* out = (float*)d_out;

    const int smem = (D_DIM * TOK_TILE + D_DIM * CPAD + KCHUNK) * 4;  // 100,608 B
    cudaFuncSetAttribute(vq_argmin_kernel, cudaFuncAttributeMaxDynamicSharedMemorySize, smem);

    vq_cnorm_kernel<<<K_DIM / 8, 256>>>(cb);
    vq_argmin_kernel<<<N_TOK / TOK_TILE, 256, smem>>>(z, cb);
    vq_gather_kernel<<<(N_TOK * D_DIM / 4) / 256, 256>>>(cb, out);
}

// round 4
// speedup vs baseline: 1.5825x; 1.1555x over previous
#include <cuda_runtime.h>
#include <cstdint>

// VectorQuantizerRestart: z [16,128,4096] fp32, codebook [1024,128] fp32
#define D_DIM 128
#define T_DIM 4096
#define K_DIM 1024
#define N_TOK 65536

__device__ float g_cnorm[K_DIM];
__device__ int   g_idx[N_TOK];
// Pre-split, fragment-ordered codebook: [chunk 16][s 16][jp 4][lane 32][q 4]
__device__ __align__(16) float g_bfrag_hi[16 * 16 * 4 * 32 * 4];
__device__ __align__(16) float g_bfrag_lo[16 * 16 * 4 * 32 * 4];

__device__ __forceinline__ uint32_t f2tf32(float x) {
    uint32_t r; asm("cvt.rna.tf32.f32 %0, %1;" : "=r"(r) : "f"(x)); return r;
}
__device__ __forceinline__ void mma_tf32(float* d, const uint32_t* a, const uint32_t* b) {
    asm volatile(
        "mma.sync.aligned.m16n8k8.row.col.f32.tf32.tf32.f32 "
        "{%0,%1,%2,%3}, {%4,%5,%6,%7}, {%8,%9}, {%0,%1,%2,%3};"
        : "+f"(d[0]), "+f"(d[1]), "+f"(d[2]), "+f"(d[3])
        : "r"(a[0]), "r"(a[1]), "r"(a[2]), "r"(a[3]), "r"(b[0]), "r"(b[1]));
}

// ---------------------------------------------------------------------------
// Kernel 1: codebook squared norms (one warp per code).
// ---------------------------------------------------------------------------
__global__ void vq_cnorm_kernel(const float* __restrict__ cb) {
    int w    = (blockIdx.x * blockDim.x + threadIdx.x) >> 5;
    int lane = threadIdx.x & 31;
    if (w >= K_DIM) return;
    float s = 0.f;
    #pragma unroll
    for (int d = lane; d < D_DIM; d += 32) {
        float v = cb[(size_t)w * D_DIM + d];
        s = fmaf(v, v, s);
    }
    #pragma unroll
    for (int o = 16; o > 0; o >>= 1) s += __shfl_xor_sync(0xffffffffu, s, o);
    if (lane == 0) g_cnorm[w] = s;
}

// ---------------------------------------------------------------------------
// Kernel 1b: split codebook into tf32 hi/lo, permuted into mma fragment order.
// Fragment map (m16n8k8 .col B): b0 = B[k = 4s*2? -> k = 8s + (lane&3) + 4*(q&1)],
// n = (jp*2 + (q>>1))*8 + (lane>>2), within chunk c of 64 codes.
// ---------------------------------------------------------------------------
__global__ void vq_bfrag_kernel(const float* __restrict__ cb) {
    int idx = blockIdx.x * blockDim.x + threadIdx.x;      // 131072 positions
    int q    = idx & 3;
    int lane = (idx >> 2) & 31;
    int jp   = (idx >> 7) & 3;
    int s    = (idx >> 9) & 15;
    int c    = idx >> 13;
    int j    = jp * 2 + (q >> 1);
    int k    = s * 8 + (lane & 3) + 4 * (q & 1);
    int code = c * 64 + j * 8 + (lane >> 2);
    float x = cb[code * D_DIM + k];
    uint32_t hi = f2tf32(x);
    float lo = x - __uint_as_float(hi);
    g_bfrag_hi[idx] = __uint_as_float(hi);
    g_bfrag_lo[idx] = __uint_as_float(f2tf32(lo));
}

// ---------------------------------------------------------------------------
// Kernel 2: 4-term TF32 mma.sync distance GEMM + inline register argmin.
// CTA: 256 thr = 8 warps = 4 mgroups x 2 ngroups; warp tile m32n32.
// SMEM: A frags [s16][mtg8][h2][lane32]f4 = 128KB, B frags [h2][s16][jp4][lane32]f4 = 64KB,
//       cnorm 4KB.  One CTA/SM.
// ---------------------------------------------------------------------------
#define A_F4   8192
#define B_F4   4096
#define SMEM_BYTES ((A_F4 + B_F4) * 16 + K_DIM * 4)   // 200704

__global__ __launch_bounds__(256, 1)
void vq_argmin_kernel(const float* __restrict__ z) {
    extern __shared__ float4 smem4[];
    float4* As = smem4;                 // [s][mtg][h][lane]
    float4* Bs = smem4 + A_F4;          // [h][s][jp][lane]
    float*  cn = reinterpret_cast<float*>(smem4 + A_F4 + B_F4);

    const int tid  = threadIdx.x;
    const int lane = tid & 31;
    const int w    = tid >> 5;
    const int mg   = w >> 1;            // 0..3
    const int ng   = w & 1;             // 0..1

    const int n0 = blockIdx.x * 128;    // 4096 % 128 == 0: no batch crossing
    const int bb = n0 >> 12;
    const int t0 = n0 & (T_DIM - 1);
    const float* zb = z + (size_t)bb * D_DIM * T_DIM + t0;

    for (int i = tid; i < K_DIM; i += 256) cn[i] = g_cnorm[i];

    // ---- A prologue: load z, split to tf32 hi/lo, store in fragment order.
    // a-regs {a0,a1,a2,a3} = z at {(k,m),(k,m+8),(k+4,m),(k+4,m+8)},
    // k = 8s + (lane&3), m = 16*mtg + (lane>>2).
    for (int p = w; p < 128; p += 8) {
        int s   = p >> 3;
        int mtg = p & 7;
        int k = s * 8 + (lane & 3);
        int m = mtg * 16 + (lane >> 2);
        float x0 = zb[k * T_DIM + m];
        float x1 = zb[k * T_DIM + m + 8];
        float x2 = zb[(k + 4) * T_DIM + m];
        float x3 = zb[(k + 4) * T_DIM + m + 8];
        uint32_t h0 = f2tf32(x0), h1 = f2tf32(x1), h2 = f2tf32(x2), h3 = f2tf32(x3);
        float4 hv, lv;
        hv.x = __uint_as_float(h0); hv.y = __uint_as_float(h1);
        hv.z = __uint_as_float(h2); hv.w = __uint_as_float(h3);
        lv.x = __uint_as_float(f2tf32(x0 - __uint_as_float(h0)));
        lv.y = __uint_as_float(f2tf32(x1 - __uint_as_float(h1)));
        lv.z = __uint_as_float(f2tf32(x2 - __uint_as_float(h2)));
        lv.w = __uint_as_float(f2tf32(x3 - __uint_as_float(h3)));
        As[((s * 8 + mtg) * 2 + 0) * 32 + lane] = hv;
        As[((s * 8 + mtg) * 2 + 1) * 32 + lane] = lv;
    }

    float minv[2][2];
    int   mini[2][2];
    #pragma unroll
    for (int a = 0; a < 2; a++)
        #pragma unroll
        for (int r = 0; r < 2; r++) { minv[a][r] = 3.4e38f; mini[a][r] = 0; }

    const uint32_t bsm = (uint32_t)__cvta_generic_to_shared(Bs);

    #pragma unroll 1
    for (int c = 0; c < 16; ++c) {
        __syncthreads();                       // all warps done reading B[c-1]
        // ---- B chunk load: raw 64KB memcpy of fragment-ordered data.
        const float* shi = g_bfrag_hi + c * 8192;
        const float* slo = g_bfrag_lo + c * 8192;
        #pragma unroll
        for (int i = 0; i < 8; ++i) {
            int e = i * 256 + tid;             // float4 index within half
            uint32_t dh = bsm + (uint32_t)e * 16u;
            uint32_t dl = bsm + (uint32_t)(2048 + e) * 16u;
            asm volatile("cp.async.cg.shared.global [%0], [%1], 16;"
                         :: "r"(dh), "l"(shi + e * 4) : "memory");
            asm volatile("cp.async.cg.shared.global [%0], [%1], 16;"
                         :: "r"(dl), "l"(slo + e * 4) : "memory");
        }
        asm volatile("cp.async.commit_group;" ::: "memory");
        asm volatile("cp.async.wait_group 0;" ::: "memory");
        __syncthreads();

        float acc[2][4][4];
        #pragma unroll
        for (int mt = 0; mt < 2; mt++)
            #pragma unroll
            for (int nt = 0; nt < 4; nt++)
                #pragma unroll
                for (int qi = 0; qi < 4; qi++) acc[mt][nt][qi] = 0.f;

        #pragma unroll 4
        for (int s = 0; s < 16; ++s) {
            uint32_t afr[2][2][4];             // [mt][h][4]
            #pragma unroll
            for (int mt = 0; mt < 2; mt++)
                #pragma unroll
                for (int h = 0; h < 2; h++) {
                    float4 v = As[((s * 8 + mg * 2 + mt) * 2 + h) * 32 + lane];
                    afr[mt][h][0] = __float_as_uint(v.x);
                    afr[mt][h][1] = __float_as_uint(v.y);
                    afr[mt][h][2] = __float_as_uint(v.z);
                    afr[mt][h][3] = __float_as_uint(v.w);
                }
            uint32_t bfr[2][2][4];             // [jl][h][4] = {j0b0,j0b1,j1b0,j1b1}
            #pragma unroll
            for (int jl = 0; jl < 2; jl++)
                #pragma unroll
                for (int h = 0; h < 2; h++) {
                    float4 v = Bs[((h * 16 + s) * 4 + ng * 2 + jl) * 32 + lane];
                    bfr[jl][h][0] = __float_as_uint(v.x);
                    bfr[jl][h][1] = __float_as_uint(v.y);
                    bfr[jl][h][2] = __float_as_uint(v.z);
                    bfr[jl][h][3] = __float_as_uint(v.w);
                }
            // 4 terms: hi*hi, hi*lo, lo*hi, lo*lo
            #pragma unroll
            for (int term = 0; term < 4; term++) {
                const int ha = term >> 1, hb = term & 1;
                #pragma unroll
                for (int jl = 0; jl < 2; jl++)
                    #pragma unroll
                    for (int jj = 0; jj < 2; jj++)
                        #pragma unroll
                        for (int mt = 0; mt < 2; mt++)
                            mma_tf32(acc[mt][jl * 2 + jj], afr[mt][ha],
                                     &bfr[jl][hb][jj * 2]);
            }
        }

        // ---- epilogue: d2 = ||c||^2 - 2*dot, running strict-< min (n ascending)
        #pragma unroll
        for (int nt = 0; nt < 4; nt++) {
            int n = c * 64 + ng * 32 + nt * 8 + 2 * (lane & 3);
            float cv0 = cn[n], cv1 = cn[n + 1];
            #pragma unroll
            for (int mt = 0; mt < 2; mt++) {
                float d00 = fmaf(-2.f, acc[mt][nt][0], cv0);
                float d01 = fmaf(-2.f, acc[mt][nt][1], cv1);
                float d10 = fmaf(-2.f, acc[mt][nt][2], cv0);
                float d11 = fmaf(-2.f, acc[mt][nt][3], cv1);
                if (d00 < minv[mt][0]) { minv[mt][0] = d00; mini[mt][0] = n; }
                if (d01 < minv[mt][0]) { minv[mt][0] = d01; mini[mt][0] = n + 1; }
                if (d10 < minv[mt][1]) { minv[mt][1] = d10; mini[mt][1] = n; }
                if (d11 < minv[mt][1]) { minv[mt][1] = d11; mini[mt][1] = n + 1; }
            }
        }
    }

    // ---- cross-thread reduce: 8 candidates per token (4 lanes x 2 ngroups)
    __syncthreads();
    float* rv = reinterpret_cast<float*>(smem4);          // [128][8]
    int*   ri = reinterpret_cast<int*>(rv + 1024);
    #pragma unroll
    for (int mt = 0; mt < 2; mt++)
        #pragma unroll
        for (int rh = 0; rh < 2; rh++) {
            int tok  = mg * 32 + mt * 16 + rh * 8 + (lane >> 2);
            int slot = ng * 4 + (lane & 3);
            rv[tok * 8 + slot] = minv[mt][rh];
            ri[tok * 8 + slot] = mini[mt][rh];
        }
    __syncthreads();
    if (tid < 128) {
        float bv = rv[tid * 8];
        int   bi = ri[tid * 8];
        #pragma unroll
        for (int x = 1; x < 8; x++) {
            float v = rv[tid * 8 + x];
            int   k = ri[tid * 8 + x];
            if (v < bv || (v == bv && k < bi)) { bv = v; bi = k; }
        }
        g_idx[n0 + tid] = bi;
    }
}

// ---------------------------------------------------------------------------
// Kernel 3: gather. 4 consecutive t per thread -> float4 store; cb L2-resident.
// ---------------------------------------------------------------------------
__global__ void vq_gather_kernel(const float* __restrict__ cb, float* __restrict__ out) {
    int gid = blockIdx.x * blockDim.x + threadIdx.x;   // over N_TOK*D/4
    int t4 = gid & (T_DIM / 4 - 1);
    int r  = gid >> 10;
    int d  = r & 127;
    int b  = r >> 7;
    const int* ip = g_idx + b * T_DIM + t4 * 4;
    float4 o;
    o.x = __ldg(cb + (size_t)ip[0] * D_DIM + d);
    o.y = __ldg(cb + (size_t)ip[1] * D_DIM + d);
    o.z = __ldg(cb + (size_t)ip[2] * D_DIM + d);
    o.w = __ldg(cb + (size_t)ip[3] * D_DIM + d);
    reinterpret_cast<float4*>(out)[gid] = o;
}

// ---------------------------------------------------------------------------
extern "C" void kernel_launch(void* const* d_in, const int* in_sizes, int n_in,
                              void* d_out, int out_size) {
    const float* z  = (const float*)d_in[0];
    const float* cb = (const float*)d_in[1];
    float* out = (float*)d_out;

    cudaFuncSetAttribute(vq_argmin_kernel,
                         cudaFuncAttributeMaxDynamicSharedMemorySize, SMEM_BYTES);

    vq_cnorm_kernel<<<K_DIM / 8, 256>>>(cb);
    vq_bfrag_kernel<<<512, 256>>>(cb);
    vq_argmin_kernel<<<N_TOK / 128, 256, SMEM_BYTES>>>(z);
    vq_gather_kernel<<<(N_TOK * D_DIM / 4) / 256, 256>>>(cb, out);
}

// round 5
// speedup vs baseline: 2.1121x; 1.3347x over previous
#include <cuda_runtime.h>
#include <cstdint>

// VectorQuantizerRestart: z [16,128,4096] fp32, codebook [1024,128] fp32
#define D_DIM 128
#define T_DIM 4096
#define K_DIM 1024
#define N_TOK 65536

__device__ float g_cnorm[K_DIM];
__device__ int   g_idx[N_TOK];
// Pre-split, fragment-ordered codebook: [chunk 16][s 16][jp 4][lane 32][q 4]
__device__ __align__(16) float g_bfrag_hi[16 * 16 * 4 * 32 * 4];
__device__ __align__(16) float g_bfrag_lo[16 * 16 * 4 * 32 * 4];

__device__ __forceinline__ uint32_t f2tf32(float x) {
    uint32_t r; asm("cvt.rna.tf32.f32 %0, %1;" : "=r"(r) : "f"(x)); return r;
}
__device__ __forceinline__ void mma_tf32(float* d, const uint32_t* a, const uint32_t* b) {
    asm volatile(
        "mma.sync.aligned.m16n8k8.row.col.f32.tf32.tf32.f32 "
        "{%0,%1,%2,%3}, {%4,%5,%6,%7}, {%8,%9}, {%0,%1,%2,%3};"
        : "+f"(d[0]), "+f"(d[1]), "+f"(d[2]), "+f"(d[3])
        : "r"(a[0]), "r"(a[1]), "r"(a[2]), "r"(a[3]), "r"(b[0]), "r"(b[1]));
}

// ---------------------------------------------------------------------------
// Kernel 1: codebook squared norms (one warp per code).
// ---------------------------------------------------------------------------
__global__ void vq_cnorm_kernel(const float* __restrict__ cb) {
    int w    = (blockIdx.x * blockDim.x + threadIdx.x) >> 5;
    int lane = threadIdx.x & 31;
    if (w >= K_DIM) return;
    float s = 0.f;
    #pragma unroll
    for (int d = lane; d < D_DIM; d += 32) {
        float v = cb[(size_t)w * D_DIM + d];
        s = fmaf(v, v, s);
    }
    #pragma unroll
    for (int o = 16; o > 0; o >>= 1) s += __shfl_xor_sync(0xffffffffu, s, o);
    if (lane == 0) g_cnorm[w] = s;
}

// ---------------------------------------------------------------------------
// Kernel 1b: split codebook into tf32 hi/lo, permuted into mma fragment order.
// b-frag (m16n8k8 .col): k = 8s + (lane&3) + 4*(q&1), n = (jp*2+(q>>1))*8 + (lane>>2)
// ---------------------------------------------------------------------------
__global__ void vq_bfrag_kernel(const float* __restrict__ cb) {
    int idx = blockIdx.x * blockDim.x + threadIdx.x;      // 131072 positions
    int q    = idx & 3;
    int lane = (idx >> 2) & 31;
    int jp   = (idx >> 7) & 3;
    int s    = (idx >> 9) & 15;
    int c    = idx >> 13;
    int j    = jp * 2 + (q >> 1);
    int k    = s * 8 + (lane & 3) + 4 * (q & 1);
    int code = c * 64 + j * 8 + (lane >> 2);
    float x = cb[code * D_DIM + k];
    uint32_t hi = f2tf32(x);
    float lo = x - __uint_as_float(hi);
    g_bfrag_hi[idx] = __uint_as_float(hi);
    g_bfrag_lo[idx] = __uint_as_float(f2tf32(lo));
}

// ---------------------------------------------------------------------------
// Kernel 2: 3-term 3xTF32 mma.sync distance GEMM + inline register argmin.
// CTA: 256 thr = 8 warps = 4 mgroups x 2 ngroups; warp tile m32n32.
// Epilogue of chunk c-1 overlaps the cp.async load of chunk c.
// ---------------------------------------------------------------------------
#define A_F4   8192
#define B_F4   4096
#define SMEM_BYTES ((A_F4 + B_F4) * 16 + K_DIM * 4)   // 200704

__global__ __launch_bounds__(256, 1)
void vq_argmin_kernel(const float* __restrict__ z) {
    extern __shared__ float4 smem4[];
    float4* As = smem4;                 // [s][mtg][h][lane]
    float4* Bs = smem4 + A_F4;          // [h][s][jp][lane]
    float*  cn = reinterpret_cast<float*>(smem4 + A_F4 + B_F4);

    const int tid  = threadIdx.x;
    const int lane = tid & 31;
    const int w    = tid >> 5;
    const int mg   = w >> 1;            // 0..3
    const int ng   = w & 1;             // 0..1

    const int n0 = blockIdx.x * 128;
    const int bb = n0 >> 12;
    const int t0 = n0 & (T_DIM - 1);
    const float* zb = z + (size_t)bb * D_DIM * T_DIM + t0;

    for (int i = tid; i < K_DIM; i += 256) cn[i] = g_cnorm[i];

    // ---- A prologue: z -> tf32 hi/lo in fragment order.
    for (int p = w; p < 128; p += 8) {
        int s   = p >> 3;
        int mtg = p & 7;
        int k = s * 8 + (lane & 3);
        int m = mtg * 16 + (lane >> 2);
        float x0 = zb[k * T_DIM + m];
        float x1 = zb[k * T_DIM + m + 8];
        float x2 = zb[(k + 4) * T_DIM + m];
        float x3 = zb[(k + 4) * T_DIM + m + 8];
        uint32_t h0 = f2tf32(x0), h1 = f2tf32(x1), h2 = f2tf32(x2), h3 = f2tf32(x3);
        float4 hv, lv;
        hv.x = __uint_as_float(h0); hv.y = __uint_as_float(h1);
        hv.z = __uint_as_float(h2); hv.w = __uint_as_float(h3);
        lv.x = __uint_as_float(f2tf32(x0 - __uint_as_float(h0)));
        lv.y = __uint_as_float(f2tf32(x1 - __uint_as_float(h1)));
        lv.z = __uint_as_float(f2tf32(x2 - __uint_as_float(h2)));
        lv.w = __uint_as_float(f2tf32(x3 - __uint_as_float(h3)));
        As[((s * 8 + mtg) * 2 + 0) * 32 + lane] = hv;
        As[((s * 8 + mtg) * 2 + 1) * 32 + lane] = lv;
    }

    float minv[2][2];
    int   mini[2][2];
    #pragma unroll
    for (int a = 0; a < 2; a++)
        #pragma unroll
        for (int r = 0; r < 2; r++) { minv[a][r] = 3.4e38f; mini[a][r] = 0; }

    const uint32_t bsm = (uint32_t)__cvta_generic_to_shared(Bs);
    float acc[2][4][4];

    #pragma unroll 1
    for (int c = 0; c < 16; ++c) {
        __syncthreads();                       // all warps done reading B[c-1]
        // ---- issue B chunk load (fragment-ordered 64KB memcpy)
        const float* shi = g_bfrag_hi + c * 8192;
        const float* slo = g_bfrag_lo + c * 8192;
        #pragma unroll
        for (int i = 0; i < 8; ++i) {
            int e = i * 256 + tid;
            uint32_t dh = bsm + (uint32_t)e * 16u;
            uint32_t dl = bsm + (uint32_t)(2048 + e) * 16u;
            asm volatile("cp.async.cg.shared.global [%0], [%1], 16;"
                         :: "r"(dh), "l"(shi + e * 4) : "memory");
            asm volatile("cp.async.cg.shared.global [%0], [%1], 16;"
                         :: "r"(dl), "l"(slo + e * 4) : "memory");
        }
        asm volatile("cp.async.commit_group;" ::: "memory");

        // ---- epilogue for chunk c-1 (registers + cn only) overlaps the load
        if (c > 0) {
            #pragma unroll
            for (int nt = 0; nt < 4; nt++) {
                int n = (c - 1) * 64 + ng * 32 + nt * 8 + 2 * (lane & 3);
                float cv0 = cn[n], cv1 = cn[n + 1];
                #pragma unroll
                for (int mt = 0; mt < 2; mt++) {
                    float d00 = fmaf(-2.f, acc[mt][nt][0], cv0);
                    float d01 = fmaf(-2.f, acc[mt][nt][1], cv1);
                    float d10 = fmaf(-2.f, acc[mt][nt][2], cv0);
                    float d11 = fmaf(-2.f, acc[mt][nt][3], cv1);
                    if (d00 < minv[mt][0]) { minv[mt][0] = d00; mini[mt][0] = n; }
                    if (d01 < minv[mt][0]) { minv[mt][0] = d01; mini[mt][0] = n + 1; }
                    if (d10 < minv[mt][1]) { minv[mt][1] = d10; mini[mt][1] = n; }
                    if (d11 < minv[mt][1]) { minv[mt][1] = d11; mini[mt][1] = n + 1; }
                }
            }
        }

        asm volatile("cp.async.wait_group 0;" ::: "memory");
        __syncthreads();

        #pragma unroll
        for (int mt = 0; mt < 2; mt++)
            #pragma unroll
            for (int nt = 0; nt < 4; nt++)
                #pragma unroll
                for (int qi = 0; qi < 4; qi++) acc[mt][nt][qi] = 0.f;

        #pragma unroll 4
        for (int s = 0; s < 16; ++s) {
            uint32_t afr[2][2][4];             // [mt][h][4]
            #pragma unroll
            for (int mt = 0; mt < 2; mt++)
                #pragma unroll
                for (int h = 0; h < 2; h++) {
                    float4 v = As[((s * 8 + mg * 2 + mt) * 2 + h) * 32 + lane];
                    afr[mt][h][0] = __float_as_uint(v.x);
                    afr[mt][h][1] = __float_as_uint(v.y);
                    afr[mt][h][2] = __float_as_uint(v.z);
                    afr[mt][h][3] = __float_as_uint(v.w);
                }
            uint32_t bfr[2][2][4];             // [jl][h][4]
            #pragma unroll
            for (int jl = 0; jl < 2; jl++)
                #pragma unroll
                for (int h = 0; h < 2; h++) {
                    float4 v = Bs[((h * 16 + s) * 4 + ng * 2 + jl) * 32 + lane];
                    bfr[jl][h][0] = __float_as_uint(v.x);
                    bfr[jl][h][1] = __float_as_uint(v.y);
                    bfr[jl][h][2] = __float_as_uint(v.z);
                    bfr[jl][h][3] = __float_as_uint(v.w);
                }
            // 3 terms: hi*hi, hi*lo, lo*hi  (lo*lo ~ 2^-24 relative: negligible)
            #pragma unroll
            for (int term = 0; term < 3; term++) {
                const int ha = (term == 2) ? 1 : 0;
                const int hb = (term == 1) ? 1 : 0;
                #pragma unroll
                for (int jl = 0; jl < 2; jl++)
                    #pragma unroll
                    for (int jj = 0; jj < 2; jj++)
                        #pragma unroll
                        for (int mt = 0; mt < 2; mt++)
                            mma_tf32(acc[mt][jl * 2 + jj], afr[mt][ha],
                                     &bfr[jl][hb][jj * 2]);
            }
        }
    }

    // final chunk epilogue
    #pragma unroll
    for (int nt = 0; nt < 4; nt++) {
        int n = 15 * 64 + ng * 32 + nt * 8 + 2 * (lane & 3);
        float cv0 = cn[n], cv1 = cn[n + 1];
        #pragma unroll
        for (int mt = 0; mt < 2; mt++) {
            float d00 = fmaf(-2.f, acc[mt][nt][0], cv0);
            float d01 = fmaf(-2.f, acc[mt][nt][1], cv1);
            float d10 = fmaf(-2.f, acc[mt][nt][2], cv0);
            float d11 = fmaf(-2.f, acc[mt][nt][3], cv1);
            if (d00 < minv[mt][0]) { minv[mt][0] = d00; mini[mt][0] = n; }
            if (d01 < minv[mt][0]) { minv[mt][0] = d01; mini[mt][0] = n + 1; }
            if (d10 < minv[mt][1]) { minv[mt][1] = d10; mini[mt][1] = n; }
            if (d11 < minv[mt][1]) { minv[mt][1] = d11; mini[mt][1] = n + 1; }
        }
    }

    // ---- cross-thread reduce: 8 candidates per token (4 lanes x 2 ngroups)
    __syncthreads();
    float* rv = reinterpret_cast<float*>(smem4);          // [128][8]
    int*   ri = reinterpret_cast<int*>(rv + 1024);
    #pragma unroll
    for (int mt = 0; mt < 2; mt++)
        #pragma unroll
        for (int rh = 0; rh < 2; rh++) {
            int tok  = mg * 32 + mt * 16 + rh * 8 + (lane >> 2);
            int slot = ng * 4 + (lane & 3);
            rv[tok * 8 + slot] = minv[mt][rh];
            ri[tok * 8 + slot] = mini[mt][rh];
        }
    __syncthreads();
    if (tid < 128) {
        float bv = rv[tid * 8];
        int   bi = ri[tid * 8];
        #pragma unroll
        for (int x = 1; x < 8; x++) {
            float v = rv[tid * 8 + x];
            int   k = ri[tid * 8 + x];
            if (v < bv || (v == bv && k < bi)) { bv = v; bi = k; }
        }
        g_idx[n0 + tid] = bi;
    }
}

// ---------------------------------------------------------------------------
// Kernel 3: gather. Warp = 32 consecutive t, 8-wide d slice per lane:
// 2x LDG.128 per lane = one full 32B sector from the indexed codebook row
// (100% sector efficiency); 8 warp-coalesced STG.32 groups on out.
// ---------------------------------------------------------------------------
__global__ void vq_gather_kernel(const float* __restrict__ cb, float* __restrict__ out) {
    int gw   = (blockIdx.x * blockDim.x + threadIdx.x) >> 5;   // 32768 warps
    int lane = threadIdx.x & 31;
    int t  = ((gw & 127) << 5) + lane;      // 0..4095
    int d0 = ((gw >> 7) & 15) << 3;         // 0..120
    int b  = gw >> 11;                      // 0..15
    int idx = g_idx[b * T_DIM + t];
    const float4* src = reinterpret_cast<const float4*>(cb + (size_t)idx * D_DIM + d0);
    float4 v0 = __ldg(src);
    float4 v1 = __ldg(src + 1);
    size_t obase = ((size_t)b * D_DIM + d0) * T_DIM + t;
    out[obase + 0 * T_DIM] = v0.x;
    out[obase + 1 * T_DIM] = v0.y;
    out[obase + 2 * T_DIM] = v0.z;
    out[obase + 3 * T_DIM] = v0.w;
    out[obase + 4 * T_DIM] = v1.x;
    out[obase + 5 * T_DIM] = v1.y;
    out[obase + 6 * T_DIM] = v1.z;
    out[obase + 7 * T_DIM] = v1.w;
}

// ---------------------------------------------------------------------------
extern "C" void kernel_launch(void* const* d_in, const int* in_sizes, int n_in,
                              void* d_out, int out_size) {
    const float* z  = (const float*)d_in[0];
    const float* cb = (const float*)d_in[1];
    float* out = (float*)d_out;

    cudaFuncSetAttribute(vq_argmin_kernel,
                         cudaFuncAttributeMaxDynamicSharedMemorySize, SMEM_BYTES);

    vq_cnorm_kernel<<<K_DIM / 8, 256>>>(cb);
    vq_bfrag_kernel<<<512, 256>>>(cb);
    vq_argmin_kernel<<<N_TOK / 128, 256, SMEM_BYTES>>>(z);
    vq_gather_kernel<<<4096, 256>>>(cb, out);
}

// round 6
// speedup vs baseline: 2.2336x; 1.0575x over previous
#include <cuda_runtime.h>
#include <cuda_bf16.h>
#include <cstdint>

// VectorQuantizerRestart: z [16,128,4096] fp32, codebook [1024,128] fp32
#define D_DIM 128
#define T_DIM 4096
#define K_DIM 1024
#define N_TOK 65536

__device__ float g_cnorm[K_DIM];
__device__ int   g_idx[N_TOK];
// bf16 3-limb codebook, fragment-ordered: [c16][s8][limb3][ntp4][lane32][q4] uint32(bf16x2)
__device__ __align__(16) uint32_t g_bfrag[16 * 8 * 3 * 4 * 32 * 4];

__device__ __forceinline__ void split3(float x, unsigned short& h,
                                       unsigned short& m, unsigned short& l) {
    __nv_bfloat16 bh = __float2bfloat16_rn(x);
    float r1 = x - __bfloat162float(bh);
    __nv_bfloat16 bm = __float2bfloat16_rn(r1);
    float r2 = r1 - __bfloat162float(bm);
    __nv_bfloat16 bl = __float2bfloat16_rn(r2);
    h = __bfloat16_as_ushort(bh);
    m = __bfloat16_as_ushort(bm);
    l = __bfloat16_as_ushort(bl);
}

__device__ __forceinline__ void mma_bf16(float* d, const uint32_t* a, const uint32_t* b) {
    asm volatile(
        "mma.sync.aligned.m16n8k16.row.col.f32.bf16.bf16.f32 "
        "{%0,%1,%2,%3}, {%4,%5,%6,%7}, {%8,%9}, {%0,%1,%2,%3};"
        : "+f"(d[0]), "+f"(d[1]), "+f"(d[2]), "+f"(d[3])
        : "r"(a[0]), "r"(a[1]), "r"(a[2]), "r"(a[3]), "r"(b[0]), "r"(b[1]));
}

// ---------------------------------------------------------------------------
// Kernel 1: codebook squared norms (one warp per code).
// ---------------------------------------------------------------------------
__global__ void vq_cnorm_kernel(const float* __restrict__ cb) {
    int w    = (blockIdx.x * blockDim.x + threadIdx.x) >> 5;
    int lane = threadIdx.x & 31;
    if (w >= K_DIM) return;
    float s = 0.f;
    #pragma unroll
    for (int d = lane; d < D_DIM; d += 32) {
        float v = cb[(size_t)w * D_DIM + d];
        s = fmaf(v, v, s);
    }
    #pragma unroll
    for (int o = 16; o > 0; o >>= 1) s += __shfl_xor_sync(0xffffffffu, s, o);
    if (lane == 0) g_cnorm[w] = s;
}

// ---------------------------------------------------------------------------
// Kernel 1b: split codebook into 3 bf16 limbs, fragment order for m16n8k16.
// b0: k=(lane&3)*2+{0,1}, b1: k+8; n = ntile*8 + (lane>>2).
// e = [c][s][limb][ntp][lane][q]: q>>1 = ntile within pair, q&1 = reg (k+8).
// ---------------------------------------------------------------------------
__global__ void vq_bfrag_kernel(const float* __restrict__ cb) {
    int e = blockIdx.x * blockDim.x + threadIdx.x;     // 196608
    int q    = e & 3;
    int lane = (e >> 2) & 31;
    int ntp  = (e >> 7) & 3;
    int rem  = e >> 9;
    int limb = rem % 3;
    int rem2 = rem / 3;
    int s    = rem2 & 7;
    int c    = rem2 >> 3;

    int n = c * 64 + (ntp * 2 + (q >> 1)) * 8 + (lane >> 2);
    int k = s * 16 + ((q & 1) << 3) + (lane & 3) * 2;
    float x0 = cb[n * D_DIM + k];
    float x1 = cb[n * D_DIM + k + 1];
    unsigned short h0, m0, l0, h1, m1, l1;
    split3(x0, h0, m0, l0);
    split3(x1, h1, m1, l1);
    unsigned short lo = (limb == 0) ? h0 : (limb == 1) ? m0 : l0;
    unsigned short hi = (limb == 0) ? h1 : (limb == 1) ? m1 : l1;
    g_bfrag[e] = (uint32_t)lo | ((uint32_t)hi << 16);
}

// ---------------------------------------------------------------------------
// Kernel 2: 6-term bf16-limb mma.sync distance GEMM + inline register argmin.
// CTA: 256 thr = 8 warps = 4 mg x 2 ng; warp tile m32n32; chunk = 64 codes.
// A (96KB, 3 limbs) resident; B double-buffered (2 x 48KB), cp.async 1 chunk ahead.
// ---------------------------------------------------------------------------
#define A_U4   6144            // uint4 count: [s8][mt8][limb3][lane32]
#define B_U4   3072            // per buffer:  [s8][limb3][ntp4][lane32]
#define SMEM_BYTES ((A_U4 + 2 * B_U4) * 16 + K_DIM * 4)   // 200704

__global__ __launch_bounds__(256, 1)
void vq_argmin_kernel(const float* __restrict__ z) {
    extern __shared__ uint4 smem4[];
    uint4* As = smem4;                       // A limbs
    uint4* Bs = smem4 + A_U4;                // 2 B buffers
    float* cn = reinterpret_cast<float*>(smem4 + A_U4 + 2 * B_U4);

    const int tid  = threadIdx.x;
    const int lane = tid & 31;
    const int w    = tid >> 5;
    const int mg   = w >> 1;                 // 0..3
    const int ng   = w & 1;                  // 0..1

    const int n0 = blockIdx.x * 128;
    const int bb = n0 >> 12;
    const int t0 = n0 & (T_DIM - 1);
    const float* zb = z + (size_t)bb * D_DIM * T_DIM + t0;

    for (int i = tid; i < K_DIM; i += 256) cn[i] = g_cnorm[i];

    // ---- A prologue: z -> 3 bf16 limbs in m16n8k16 fragment order.
    // a0:(m,k..k+1) a1:(m+8,k..) a2:(m,k+8..) a3:(m+8,k+8..); m=mt*16+(lane>>2), k=s*16+(lane&3)*2
    for (int p = w; p < 64; p += 8) {
        int s  = p >> 3;
        int mt = p & 7;
        int m = mt * 16 + (lane >> 2);
        int k = s * 16 + (lane & 3) * 2;
        float xv[8];
        xv[0] = zb[(k    ) * T_DIM + m    ];  xv[1] = zb[(k + 1) * T_DIM + m    ];
        xv[2] = zb[(k    ) * T_DIM + m + 8];  xv[3] = zb[(k + 1) * T_DIM + m + 8];
        xv[4] = zb[(k + 8) * T_DIM + m    ];  xv[5] = zb[(k + 9) * T_DIM + m    ];
        xv[6] = zb[(k + 8) * T_DIM + m + 8];  xv[7] = zb[(k + 9) * T_DIM + m + 8];
        unsigned short hh[8], mm[8], ll[8];
        #pragma unroll
        for (int i = 0; i < 8; i++) split3(xv[i], hh[i], mm[i], ll[i]);
        #pragma unroll
        for (int limb = 0; limb < 3; limb++) {
            const unsigned short* u = (limb == 0) ? hh : (limb == 1) ? mm : ll;
            uint4 v;
            v.x = (uint32_t)u[0] | ((uint32_t)u[1] << 16);   // a0
            v.y = (uint32_t)u[2] | ((uint32_t)u[3] << 16);   // a1
            v.z = (uint32_t)u[4] | ((uint32_t)u[5] << 16);   // a2
            v.w = (uint32_t)u[6] | ((uint32_t)u[7] << 16);   // a3
            As[((s * 8 + mt) * 3 + limb) * 32 + lane] = v;
        }
    }

    float minv[2][2];
    int   mini[2][2];
    #pragma unroll
    for (int a = 0; a < 2; a++)
        #pragma unroll
        for (int r = 0; r < 2; r++) { minv[a][r] = 3.4e38f; mini[a][r] = 0; }

    const uint32_t bsm = (uint32_t)__cvta_generic_to_shared(Bs);
    const float4*  bsrc = reinterpret_cast<const float4*>(g_bfrag);

    // prefetch chunk 0 into buffer 0
    #pragma unroll
    for (int i = 0; i < 12; ++i) {
        int e = i * 256 + tid;
        asm volatile("cp.async.cg.shared.global [%0], [%1], 16;"
                     :: "r"(bsm + (uint32_t)e * 16u), "l"(bsrc + e) : "memory");
    }
    asm volatile("cp.async.commit_group;" ::: "memory");

    static const int TLA[6] = {0, 0, 1, 0, 2, 1};
    static const int TLB[6] = {0, 1, 0, 2, 0, 1};

    #pragma unroll 1
    for (int c = 0; c < 16; ++c) {
        if (c < 15) {        // prefetch c+1 into the buffer chunk c-1 vacated
            int buf1 = (c + 1) & 1;
            const float4* src = bsrc + (c + 1) * B_U4;
            #pragma unroll
            for (int i = 0; i < 12; ++i) {
                int e = i * 256 + tid;
                asm volatile("cp.async.cg.shared.global [%0], [%1], 16;"
                             :: "r"(bsm + (uint32_t)(buf1 * B_U4 + e) * 16u),
                                "l"(src + e) : "memory");
            }
            asm volatile("cp.async.commit_group;" ::: "memory");
            asm volatile("cp.async.wait_group 1;" ::: "memory");
        } else {
            asm volatile("cp.async.wait_group 0;" ::: "memory");
        }
        __syncthreads();                       // buf[c&1] visible; A visible (c=0)

        const uint4* Bb = Bs + (c & 1) * B_U4;
        float acc[2][4][4];
        #pragma unroll
        for (int mt = 0; mt < 2; mt++)
            #pragma unroll
            for (int nt = 0; nt < 4; nt++)
                #pragma unroll
                for (int qi = 0; qi < 4; qi++) acc[mt][nt][qi] = 0.f;

        #pragma unroll 4
        for (int s = 0; s < 8; ++s) {
            uint32_t afr[2][3][4];
            #pragma unroll
            for (int mt = 0; mt < 2; mt++)
                #pragma unroll
                for (int limb = 0; limb < 3; limb++) {
                    uint4 v = As[((s * 8 + mg * 2 + mt) * 3 + limb) * 32 + lane];
                    afr[mt][limb][0] = v.x; afr[mt][limb][1] = v.y;
                    afr[mt][limb][2] = v.z; afr[mt][limb][3] = v.w;
                }
            uint32_t bfr[3][4][2];
            #pragma unroll
            for (int limb = 0; limb < 3; limb++)
                #pragma unroll
                for (int half = 0; half < 2; half++) {
                    uint4 v = Bb[((s * 3 + limb) * 4 + ng * 2 + half) * 32 + lane];
                    bfr[limb][half * 2    ][0] = v.x; bfr[limb][half * 2    ][1] = v.y;
                    bfr[limb][half * 2 + 1][0] = v.z; bfr[limb][half * 2 + 1][1] = v.w;
                }
            // 6 terms: h*h, h*m, m*h, h*l, l*h, m*m
            #pragma unroll
            for (int term = 0; term < 6; term++) {
                const int la = TLA[term], lb = TLB[term];
                #pragma unroll
                for (int nt = 0; nt < 4; nt++)
                    #pragma unroll
                    for (int mt = 0; mt < 2; mt++)
                        mma_bf16(acc[mt][nt], afr[mt][la], bfr[lb][nt]);
            }
        }

        // ---- epilogue: d2 = ||c||^2 - 2*dot, strict-< running min (n ascending)
        #pragma unroll
        for (int nt = 0; nt < 4; nt++) {
            int n = c * 64 + ng * 32 + nt * 8 + 2 * (lane & 3);
            float cv0 = cn[n], cv1 = cn[n + 1];
            #pragma unroll
            for (int mt = 0; mt < 2; mt++) {
                float d00 = fmaf(-2.f, acc[mt][nt][0], cv0);
                float d01 = fmaf(-2.f, acc[mt][nt][1], cv1);
                float d10 = fmaf(-2.f, acc[mt][nt][2], cv0);
                float d11 = fmaf(-2.f, acc[mt][nt][3], cv1);
                if (d00 < minv[mt][0]) { minv[mt][0] = d00; mini[mt][0] = n; }
                if (d01 < minv[mt][0]) { minv[mt][0] = d01; mini[mt][0] = n + 1; }
                if (d10 < minv[mt][1]) { minv[mt][1] = d10; mini[mt][1] = n; }
                if (d11 < minv[mt][1]) { minv[mt][1] = d11; mini[mt][1] = n + 1; }
            }
        }
        __syncthreads();                       // done reading buf[c&1] before overwrite
    }

    // ---- cross-thread reduce: 8 candidates per token (4 lanes x 2 ngroups)
    float* rv = reinterpret_cast<float*>(smem4);          // [128][8]
    int*   ri = reinterpret_cast<int*>(rv + 1024);
    #pragma unroll
    for (int mt = 0; mt < 2; mt++)
        #pragma unroll
        for (int rh = 0; rh < 2; rh++) {
            int tok  = mg * 32 + mt * 16 + rh * 8 + (lane >> 2);
            int slot = ng * 4 + (lane & 3);
            rv[tok * 8 + slot] = minv[mt][rh];
            ri[tok * 8 + slot] = mini[mt][rh];
        }
    __syncthreads();
    if (tid < 128) {
        float bv = rv[tid * 8];
        int   bi = ri[tid * 8];
        #pragma unroll
        for (int x = 1; x < 8; x++) {
            float v = rv[tid * 8 + x];
            int   k = ri[tid * 8 + x];
            if (v < bv || (v == bv && k < bi)) { bv = v; bi = k; }
        }
        g_idx[n0 + tid] = bi;
    }
}

// ---------------------------------------------------------------------------
// Kernel 3: gather. Warp = 32 consecutive t, 8-wide d slice per lane.
// ---------------------------------------------------------------------------
__global__ void vq_gather_kernel(const float* __restrict__ cb, float* __restrict__ out) {
    int gw   = (blockIdx.x * blockDim.x + threadIdx.x) >> 5;   // 32768 warps
    int lane = threadIdx.x & 31;
    int t  = ((gw & 127) << 5) + lane;
    int d0 = ((gw >> 7) & 15) << 3;
    int b  = gw >> 11;
    int idx = g_idx[b * T_DIM + t];
    const float4* src = reinterpret_cast<const float4*>(cb + (size_t)idx * D_DIM + d0);
    float4 v0 = __ldg(src);
    float4 v1 = __ldg(src + 1);
    size_t obase = ((size_t)b * D_DIM + d0) * T_DIM + t;
    out[obase + 0 * T_DIM] = v0.x;
    out[obase + 1 * T_DIM] = v0.y;
    out[obase + 2 * T_DIM] = v0.z;
    out[obase + 3 * T_DIM] = v0.w;
    out[obase + 4 * T_DIM] = v1.x;
    out[obase + 5 * T_DIM] = v1.y;
    out[obase + 6 * T_DIM] = v1.z;
    out[obase + 7 * T_DIM] = v1.w;
}

// ---------------------------------------------------------------------------
extern "C" void kernel_launch(void* const* d_in, const int* in_sizes, int n_in,
                              void* d_out, int out_size) {
    const float* z  = (const float*)d_in[0];
    const float* cb = (const float*)d_in[1];
    float* out = (float*)d_out;

    cudaFuncSetAttribute(vq_argmin_kernel,
                         cudaFuncAttributeMaxDynamicSharedMemorySize, SMEM_BYTES);

    vq_cnorm_kernel<<<K_DIM / 8, 256>>>(cb);
    vq_bfrag_kernel<<<768, 256>>>(cb);
    vq_argmin_kernel<<<N_TOK / 128, 256, SMEM_BYTES>>>(z);
    vq_gather_kernel<<<4096, 256>>>(cb, out);
}

// round 7
// speedup vs baseline: 2.3792x; 1.0652x over previous
#include <cuda_runtime.h>
#include <cuda_bf16.h>
#include <cstdint>

// VectorQuantizerRestart: z [16,128,4096] fp32, codebook [1024,128] fp32
#define D_DIM 128
#define T_DIM 4096
#define K_DIM 1024
#define N_TOK 65536

__device__ float g_cnorm[K_DIM];
// split-K candidates: [half 2][token]
__device__ float g_cv[2 * N_TOK];
__device__ int   g_ci[2 * N_TOK];
// bf16 3-limb codebook, fragment-ordered: [c16][s8][limb3][ntp4][lane32][q4] uint32(bf16x2)
__device__ __align__(16) uint32_t g_bfrag[16 * 8 * 3 * 4 * 32 * 4];

__device__ __forceinline__ void split3(float x, unsigned short& h,
                                       unsigned short& m, unsigned short& l) {
    __nv_bfloat16 bh = __float2bfloat16_rn(x);
    float r1 = x - __bfloat162float(bh);
    __nv_bfloat16 bm = __float2bfloat16_rn(r1);
    float r2 = r1 - __bfloat162float(bm);
    __nv_bfloat16 bl = __float2bfloat16_rn(r2);
    h = __bfloat16_as_ushort(bh);
    m = __bfloat16_as_ushort(bm);
    l = __bfloat16_as_ushort(bl);
}

__device__ __forceinline__ void mma_bf16(float* d, const uint32_t* a, const uint32_t* b) {
    asm volatile(
        "mma.sync.aligned.m16n8k16.row.col.f32.bf16.bf16.f32 "
        "{%0,%1,%2,%3}, {%4,%5,%6,%7}, {%8,%9}, {%0,%1,%2,%3};"
        : "+f"(d[0]), "+f"(d[1]), "+f"(d[2]), "+f"(d[3])
        : "r"(a[0]), "r"(a[1]), "r"(a[2]), "r"(a[3]), "r"(b[0]), "r"(b[1]));
}

// ---------------------------------------------------------------------------
// Kernel 1: codebook squared norms (one warp per code).
// ---------------------------------------------------------------------------
__global__ void vq_cnorm_kernel(const float* __restrict__ cb) {
    int w    = (blockIdx.x * blockDim.x + threadIdx.x) >> 5;
    int lane = threadIdx.x & 31;
    if (w >= K_DIM) return;
    float s = 0.f;
    #pragma unroll
    for (int d = lane; d < D_DIM; d += 32) {
        float v = cb[(size_t)w * D_DIM + d];
        s = fmaf(v, v, s);
    }
    #pragma unroll
    for (int o = 16; o > 0; o >>= 1) s += __shfl_xor_sync(0xffffffffu, s, o);
    if (lane == 0) g_cnorm[w] = s;
}

// ---------------------------------------------------------------------------
// Kernel 1b: split codebook into 3 bf16 limbs, fragment order for m16n8k16.
// ---------------------------------------------------------------------------
__global__ void vq_bfrag_kernel(const float* __restrict__ cb) {
    int e = blockIdx.x * blockDim.x + threadIdx.x;     // 196608
    int q    = e & 3;
    int lane = (e >> 2) & 31;
    int ntp  = (e >> 7) & 3;
    int rem  = e >> 9;
    int limb = rem % 3;
    int rem2 = rem / 3;
    int s    = rem2 & 7;
    int c    = rem2 >> 3;

    int n = c * 64 + (ntp * 2 + (q >> 1)) * 8 + (lane >> 2);
    int k = s * 16 + ((q & 1) << 3) + (lane & 3) * 2;
    float x0 = cb[n * D_DIM + k];
    float x1 = cb[n * D_DIM + k + 1];
    unsigned short h0, m0, l0, h1, m1, l1;
    split3(x0, h0, m0, l0);
    split3(x1, h1, m1, l1);
    unsigned short lo = (limb == 0) ? h0 : (limb == 1) ? m0 : l0;
    unsigned short hi = (limb == 0) ? h1 : (limb == 1) ? m1 : l1;
    g_bfrag[e] = (uint32_t)lo | ((uint32_t)hi << 16);
}

// ---------------------------------------------------------------------------
// Kernel 2: 6-term bf16-limb mma.sync + register argmin, SPLIT-K over codes.
// grid = 1024: blockIdx = tile*2 + half; each CTA covers 512 codes (8 chunks).
// CTA: 256 thr = 8 warps = 4 mg x 2 ng; warp tile m32n32; chunk = 64 codes.
// A (96KB, 3 limbs) resident; B double-buffered (2 x 48KB), cp.async 1 ahead.
// ---------------------------------------------------------------------------
#define A_U4   6144            // uint4: [s8][mt8][limb3][lane32]
#define B_U4   3072            // per buffer: [s8][limb3][ntp4][lane32]
#define SMEM_BYTES ((A_U4 + 2 * B_U4) * 16 + 512 * 4)   // 198656

__global__ __launch_bounds__(256, 1)
void vq_argmin_kernel(const float* __restrict__ z) {
    extern __shared__ uint4 smem4[];
    uint4* As = smem4;
    uint4* Bs = smem4 + A_U4;
    float* cn = reinterpret_cast<float*>(smem4 + A_U4 + 2 * B_U4);

    const int tid  = threadIdx.x;
    const int lane = tid & 31;
    const int w    = tid >> 5;
    const int mg   = w >> 1;
    const int ng   = w & 1;

    const int tile = blockIdx.x >> 1;
    const int half = blockIdx.x & 1;
    const int n0 = tile * 128;
    const int kb0 = half * 512;              // first code of this CTA's half
    const int bb = n0 >> 12;
    const int t0 = n0 & (T_DIM - 1);
    const float* zb = z + (size_t)bb * D_DIM * T_DIM + t0;

    for (int i = tid; i < 512; i += 256) cn[i] = g_cnorm[kb0 + i];

    // ---- A prologue: z -> 3 bf16 limbs in m16n8k16 fragment order.
    for (int p = w; p < 64; p += 8) {
        int s  = p >> 3;
        int mt = p & 7;
        int m = mt * 16 + (lane >> 2);
        int k = s * 16 + (lane & 3) * 2;
        float xv[8];
        xv[0] = zb[(k    ) * T_DIM + m    ];  xv[1] = zb[(k + 1) * T_DIM + m    ];
        xv[2] = zb[(k    ) * T_DIM + m + 8];  xv[3] = zb[(k + 1) * T_DIM + m + 8];
        xv[4] = zb[(k + 8) * T_DIM + m    ];  xv[5] = zb[(k + 9) * T_DIM + m    ];
        xv[6] = zb[(k + 8) * T_DIM + m + 8];  xv[7] = zb[(k + 9) * T_DIM + m + 8];
        unsigned short hh[8], mm[8], ll[8];
        #pragma unroll
        for (int i = 0; i < 8; i++) split3(xv[i], hh[i], mm[i], ll[i]);
        #pragma unroll
        for (int limb = 0; limb < 3; limb++) {
            const unsigned short* u = (limb == 0) ? hh : (limb == 1) ? mm : ll;
            uint4 v;
            v.x = (uint32_t)u[0] | ((uint32_t)u[1] << 16);
            v.y = (uint32_t)u[2] | ((uint32_t)u[3] << 16);
            v.z = (uint32_t)u[4] | ((uint32_t)u[5] << 16);
            v.w = (uint32_t)u[6] | ((uint32_t)u[7] << 16);
            As[((s * 8 + mt) * 3 + limb) * 32 + lane] = v;
        }
    }

    float minv[2][2];
    int   mini[2][2];
    #pragma unroll
    for (int a = 0; a < 2; a++)
        #pragma unroll
        for (int r = 0; r < 2; r++) { minv[a][r] = 3.4e38f; mini[a][r] = 0; }

    const uint32_t bsm = (uint32_t)__cvta_generic_to_shared(Bs);
    const float4*  bsrc = reinterpret_cast<const float4*>(g_bfrag) + half * 8 * B_U4;

    // prefetch local chunk 0 into buffer 0
    #pragma unroll
    for (int i = 0; i < 12; ++i) {
        int e = i * 256 + tid;
        asm volatile("cp.async.cg.shared.global [%0], [%1], 16;"
                     :: "r"(bsm + (uint32_t)e * 16u), "l"(bsrc + e) : "memory");
    }
    asm volatile("cp.async.commit_group;" ::: "memory");

    static const int TLA[6] = {0, 0, 1, 0, 2, 1};
    static const int TLB[6] = {0, 1, 0, 2, 0, 1};

    #pragma unroll 1
    for (int c = 0; c < 8; ++c) {
        if (c < 7) {
            int buf1 = (c + 1) & 1;
            const float4* src = bsrc + (c + 1) * B_U4;
            #pragma unroll
            for (int i = 0; i < 12; ++i) {
                int e = i * 256 + tid;
                asm volatile("cp.async.cg.shared.global [%0], [%1], 16;"
                             :: "r"(bsm + (uint32_t)(buf1 * B_U4 + e) * 16u),
                                "l"(src + e) : "memory");
            }
            asm volatile("cp.async.commit_group;" ::: "memory");
            asm volatile("cp.async.wait_group 1;" ::: "memory");
        } else {
            asm volatile("cp.async.wait_group 0;" ::: "memory");
        }
        __syncthreads();

        const uint4* Bb = Bs + (c & 1) * B_U4;
        float acc[2][4][4];
        #pragma unroll
        for (int mt = 0; mt < 2; mt++)
            #pragma unroll
            for (int nt = 0; nt < 4; nt++)
                #pragma unroll
                for (int qi = 0; qi < 4; qi++) acc[mt][nt][qi] = 0.f;

        #pragma unroll
        for (int s = 0; s < 8; ++s) {
            uint32_t afr[2][3][4];
            #pragma unroll
            for (int mt = 0; mt < 2; mt++)
                #pragma unroll
                for (int limb = 0; limb < 3; limb++) {
                    uint4 v = As[((s * 8 + mg * 2 + mt) * 3 + limb) * 32 + lane];
                    afr[mt][limb][0] = v.x; afr[mt][limb][1] = v.y;
                    afr[mt][limb][2] = v.z; afr[mt][limb][3] = v.w;
                }
            uint32_t bfr[3][4][2];
            #pragma unroll
            for (int limb = 0; limb < 3; limb++)
                #pragma unroll
                for (int hf = 0; hf < 2; hf++) {
                    uint4 v = Bb[((s * 3 + limb) * 4 + ng * 2 + hf) * 32 + lane];
                    bfr[limb][hf * 2    ][0] = v.x; bfr[limb][hf * 2    ][1] = v.y;
                    bfr[limb][hf * 2 + 1][0] = v.z; bfr[limb][hf * 2 + 1][1] = v.w;
                }
            #pragma unroll
            for (int term = 0; term < 6; term++) {
                const int la = TLA[term], lb = TLB[term];
                #pragma unroll
                for (int nt = 0; nt < 4; nt++)
                    #pragma unroll
                    for (int mt = 0; mt < 2; mt++)
                        mma_bf16(acc[mt][nt], afr[mt][la], bfr[lb][nt]);
            }
        }

        // ---- epilogue: d2 = ||c||^2 - 2*dot, strict-< running min (n ascending)
        #pragma unroll
        for (int nt = 0; nt < 4; nt++) {
            int nl = c * 64 + ng * 32 + nt * 8 + 2 * (lane & 3);   // local code idx
            float cv0 = cn[nl], cv1 = cn[nl + 1];
            int n = kb0 + nl;
            #pragma unroll
            for (int mt = 0; mt < 2; mt++) {
                float d00 = fmaf(-2.f, acc[mt][nt][0], cv0);
                float d01 = fmaf(-2.f, acc[mt][nt][1], cv1);
                float d10 = fmaf(-2.f, acc[mt][nt][2], cv0);
                float d11 = fmaf(-2.f, acc[mt][nt][3], cv1);
                if (d00 < minv[mt][0]) { minv[mt][0] = d00; mini[mt][0] = n; }
                if (d01 < minv[mt][0]) { minv[mt][0] = d01; mini[mt][0] = n + 1; }
                if (d10 < minv[mt][1]) { minv[mt][1] = d10; mini[mt][1] = n; }
                if (d11 < minv[mt][1]) { minv[mt][1] = d11; mini[mt][1] = n + 1; }
            }
        }
        __syncthreads();
    }

    // ---- cross-thread reduce: 8 candidates per token -> g_cv/g_ci[half]
    float* rv = reinterpret_cast<float*>(smem4);          // [128][8]
    int*   ri = reinterpret_cast<int*>(rv + 1024);
    #pragma unroll
    for (int mt = 0; mt < 2; mt++)
        #pragma unroll
        for (int rh = 0; rh < 2; rh++) {
            int tok  = mg * 32 + mt * 16 + rh * 8 + (lane >> 2);
            int slot = ng * 4 + (lane & 3);
            rv[tok * 8 + slot] = minv[mt][rh];
            ri[tok * 8 + slot] = mini[mt][rh];
        }
    __syncthreads();
    if (tid < 128) {
        float bv = rv[tid * 8];
        int   bi = ri[tid * 8];
        #pragma unroll
        for (int x = 1; x < 8; x++) {
            float v = rv[tid * 8 + x];
            int   k = ri[tid * 8 + x];
            if (v < bv || (v == bv && k < bi)) { bv = v; bi = k; }
        }
        g_cv[half * N_TOK + n0 + tid] = bv;
        g_ci[half * N_TOK + n0 + tid] = bi;
    }
}

// ---------------------------------------------------------------------------
// Kernel 3: gather + split-K merge. Warp = 32 consecutive t, 8-wide d slice.
// half0 indices < half1, so half0 wins ties (first-min semantics).
// ---------------------------------------------------------------------------
__global__ void vq_gather_kernel(const float* __restrict__ cb, float* __restrict__ out) {
    int gw   = (blockIdx.x * blockDim.x + threadIdx.x) >> 5;   // 32768 warps
    int lane = threadIdx.x & 31;
    int t  = ((gw & 127) << 5) + lane;
    int d0 = ((gw >> 7) & 15) << 3;
    int b  = gw >> 11;
    int tg = b * T_DIM + t;
    float v0 = g_cv[tg], v1 = g_cv[N_TOK + tg];
    int idx = (v1 < v0) ? g_ci[N_TOK + tg] : g_ci[tg];
    const float4* src = reinterpret_cast<const float4*>(cb + (size_t)idx * D_DIM + d0);
    float4 w0 = __ldg(src);
    float4 w1 = __ldg(src + 1);
    size_t obase = ((size_t)b * D_DIM + d0) * T_DIM + t;
    out[obase + 0 * T_DIM] = w0.x;
    out[obase + 1 * T_DIM] = w0.y;
    out[obase + 2 * T_DIM] = w0.z;
    out[obase + 3 * T_DIM] = w0.w;
    out[obase + 4 * T_DIM] = w1.x;
    out[obase + 5 * T_DIM] = w1.y;
    out[obase + 6 * T_DIM] = w1.z;
    out[obase + 7 * T_DIM] = w1.w;
}

// ---------------------------------------------------------------------------
extern "C" void kernel_launch(void* const* d_in, const int* in_sizes, int n_in,
                              void* d_out, int out_size) {
    const float* z  = (const float*)d_in[0];
    const float* cb = (const float*)d_in[1];
    float* out = (float*)d_out;

    cudaFuncSetAttribute(vq_argmin_kernel,
                         cudaFuncAttributeMaxDynamicSharedMemorySize, SMEM_BYTES);

    vq_cnorm_kernel<<<K_DIM / 8, 256>>>(cb);
    vq_bfrag_kernel<<<768, 256>>>(cb);
    vq_argmin_kernel<<<(N_TOK / 128) * 2, 256, SMEM_BYTES>>>(z);
    vq_gather_kernel<<<4096, 256>>>(cb, out);
}

// round 8
// speedup vs baseline: 2.4335x; 1.0228x over previous
#include <cuda_runtime.h>
#include <cuda_bf16.h>
#include <cstdint>

// VectorQuantizerRestart: z [16,128,4096] fp32, codebook [1024,128] fp32
#define D_DIM 128
#define T_DIM 4096
#define K_DIM 1024
#define N_TOK 65536

__device__ float g_cnorm[K_DIM];
// split-K candidates: [half 2][token]
__device__ float g_cv[2 * N_TOK];
__device__ int   g_ci[2 * N_TOK];
// bf16 3-limb codebook, fragment-ordered: [c16][s8][limb3][ntp4][lane32][q4] uint32(bf16x2)
__device__ __align__(16) uint32_t g_bfrag[16 * 8 * 3 * 4 * 32 * 4];

__device__ __forceinline__ void split3(float x, unsigned short& h,
                                       unsigned short& m, unsigned short& l) {
    __nv_bfloat16 bh = __float2bfloat16_rn(x);
    float r1 = x - __bfloat162float(bh);
    __nv_bfloat16 bm = __float2bfloat16_rn(r1);
    float r2 = r1 - __bfloat162float(bm);
    __nv_bfloat16 bl = __float2bfloat16_rn(r2);
    h = __bfloat16_as_ushort(bh);
    m = __bfloat16_as_ushort(bm);
    l = __bfloat16_as_ushort(bl);
}

__device__ __forceinline__ void mma_bf16(float* d, const uint32_t* a, const uint32_t* b) {
    asm volatile(
        "mma.sync.aligned.m16n8k16.row.col.f32.bf16.bf16.f32 "
        "{%0,%1,%2,%3}, {%4,%5,%6,%7}, {%8,%9}, {%0,%1,%2,%3};"
        : "+f"(d[0]), "+f"(d[1]), "+f"(d[2]), "+f"(d[3])
        : "r"(a[0]), "r"(a[1]), "r"(a[2]), "r"(a[3]), "r"(b[0]), "r"(b[1]));
}

// ---------------------------------------------------------------------------
// Kernel 1: codebook squared norms (one warp per code).
// ---------------------------------------------------------------------------
__global__ void vq_cnorm_kernel(const float* __restrict__ cb) {
    int w    = (blockIdx.x * blockDim.x + threadIdx.x) >> 5;
    int lane = threadIdx.x & 31;
    if (w >= K_DIM) return;
    float s = 0.f;
    #pragma unroll
    for (int d = lane; d < D_DIM; d += 32) {
        float v = cb[(size_t)w * D_DIM + d];
        s = fmaf(v, v, s);
    }
    #pragma unroll
    for (int o = 16; o > 0; o >>= 1) s += __shfl_xor_sync(0xffffffffu, s, o);
    if (lane == 0) g_cnorm[w] = s;
}

// ---------------------------------------------------------------------------
// Kernel 1b: split codebook into 3 bf16 limbs, fragment order for m16n8k16.
// ---------------------------------------------------------------------------
__global__ void vq_bfrag_kernel(const float* __restrict__ cb) {
    int e = blockIdx.x * blockDim.x + threadIdx.x;     // 196608
    int q    = e & 3;
    int lane = (e >> 2) & 31;
    int ntp  = (e >> 7) & 3;
    int rem  = e >> 9;
    int limb = rem % 3;
    int rem2 = rem / 3;
    int s    = rem2 & 7;
    int c    = rem2 >> 3;

    int n = c * 64 + (ntp * 2 + (q >> 1)) * 8 + (lane >> 2);
    int k = s * 16 + ((q & 1) << 3) + (lane & 3) * 2;
    float x0 = cb[n * D_DIM + k];
    float x1 = cb[n * D_DIM + k + 1];
    unsigned short h0, m0, l0, h1, m1, l1;
    split3(x0, h0, m0, l0);
    split3(x1, h1, m1, l1);
    unsigned short lo = (limb == 0) ? h0 : (limb == 1) ? m0 : l0;
    unsigned short hi = (limb == 0) ? h1 : (limb == 1) ? m1 : l1;
    g_bfrag[e] = (uint32_t)lo | ((uint32_t)hi << 16);
}

// ---------------------------------------------------------------------------
// Kernel 2: 6-term bf16-limb mma.sync + register argmin, split-K over codes.
// grid = 1024: blockIdx = tile*2 + half; each CTA covers 512 codes (8 chunks).
// CTA: 512 thr = 16 warps = 8 mg x 2 ng (4 warps/SMSP); warp tile m16n32.
// A (96KB, 3 limbs) resident; B double-buffered (2 x 48KB), cp.async 1 ahead.
// ---------------------------------------------------------------------------
#define A_U4   6144            // uint4: [s8][mt8][limb3][lane32]
#define B_U4   3072            // per buffer: [s8][limb3][ntp4][lane32]
#define SMEM_BYTES ((A_U4 + 2 * B_U4) * 16 + 512 * 4)   // 198656

__global__ __launch_bounds__(512, 1)
void vq_argmin_kernel(const float* __restrict__ z) {
    extern __shared__ uint4 smem4[];
    uint4* As = smem4;
    uint4* Bs = smem4 + A_U4;
    float* cn = reinterpret_cast<float*>(smem4 + A_U4 + 2 * B_U4);

    const int tid  = threadIdx.x;
    const int lane = tid & 31;
    const int w    = tid >> 5;
    const int mg   = w >> 1;                 // 0..7  (m16 tile)
    const int ng   = w & 1;                  // 0..1  (n32 tile)

    const int tile = blockIdx.x >> 1;
    const int half = blockIdx.x & 1;
    const int n0 = tile * 128;
    const int kb0 = half * 512;
    const int bb = n0 >> 12;
    const int t0 = n0 & (T_DIM - 1);
    const float* zb = z + (size_t)bb * D_DIM * T_DIM + t0;

    if (tid < 512) cn[tid] = g_cnorm[kb0 + tid];

    // ---- A prologue: z -> 3 bf16 limbs in m16n8k16 fragment order.
    for (int p = w; p < 64; p += 16) {
        int s  = p >> 3;
        int mt = p & 7;
        int m = mt * 16 + (lane >> 2);
        int k = s * 16 + (lane & 3) * 2;
        float xv[8];
        xv[0] = zb[(k    ) * T_DIM + m    ];  xv[1] = zb[(k + 1) * T_DIM + m    ];
        xv[2] = zb[(k    ) * T_DIM + m + 8];  xv[3] = zb[(k + 1) * T_DIM + m + 8];
        xv[4] = zb[(k + 8) * T_DIM + m    ];  xv[5] = zb[(k + 9) * T_DIM + m    ];
        xv[6] = zb[(k + 8) * T_DIM + m + 8];  xv[7] = zb[(k + 9) * T_DIM + m + 8];
        unsigned short hh[8], mm[8], ll[8];
        #pragma unroll
        for (int i = 0; i < 8; i++) split3(xv[i], hh[i], mm[i], ll[i]);
        #pragma unroll
        for (int limb = 0; limb < 3; limb++) {
            const unsigned short* u = (limb == 0) ? hh : (limb == 1) ? mm : ll;
            uint4 v;
            v.x = (uint32_t)u[0] | ((uint32_t)u[1] << 16);
            v.y = (uint32_t)u[2] | ((uint32_t)u[3] << 16);
            v.z = (uint32_t)u[4] | ((uint32_t)u[5] << 16);
            v.w = (uint32_t)u[6] | ((uint32_t)u[7] << 16);
            As[((s * 8 + mt) * 3 + limb) * 32 + lane] = v;
        }
    }

    float minv[2];
    int   mini[2];
    minv[0] = minv[1] = 3.4e38f;
    mini[0] = mini[1] = 0;

    const uint32_t bsm = (uint32_t)__cvta_generic_to_shared(Bs);
    const float4*  bsrc = reinterpret_cast<const float4*>(g_bfrag) + half * 8 * B_U4;

    // prefetch local chunk 0 into buffer 0 (3072 u4 / 512 thr = 6 each)
    #pragma unroll
    for (int i = 0; i < 6; ++i) {
        int e = i * 512 + tid;
        asm volatile("cp.async.cg.shared.global [%0], [%1], 16;"
                     :: "r"(bsm + (uint32_t)e * 16u), "l"(bsrc + e) : "memory");
    }
    asm volatile("cp.async.commit_group;" ::: "memory");

    static const int TLA[6] = {0, 0, 1, 0, 2, 1};
    static const int TLB[6] = {0, 1, 0, 2, 0, 1};

    #pragma unroll 1
    for (int c = 0; c < 8; ++c) {
        if (c < 7) {
            int buf1 = (c + 1) & 1;
            const float4* src = bsrc + (c + 1) * B_U4;
            #pragma unroll
            for (int i = 0; i < 6; ++i) {
                int e = i * 512 + tid;
                asm volatile("cp.async.cg.shared.global [%0], [%1], 16;"
                             :: "r"(bsm + (uint32_t)(buf1 * B_U4 + e) * 16u),
                                "l"(src + e) : "memory");
            }
            asm volatile("cp.async.commit_group;" ::: "memory");
            asm volatile("cp.async.wait_group 1;" ::: "memory");
        } else {
            asm volatile("cp.async.wait_group 0;" ::: "memory");
        }
        __syncthreads();

        const uint4* Bb = Bs + (c & 1) * B_U4;
        float acc[4][4];
        #pragma unroll
        for (int nt = 0; nt < 4; nt++)
            #pragma unroll
            for (int qi = 0; qi < 4; qi++) acc[nt][qi] = 0.f;

        #pragma unroll
        for (int s = 0; s < 8; ++s) {
            uint32_t afr[3][4];
            #pragma unroll
            for (int limb = 0; limb < 3; limb++) {
                uint4 v = As[((s * 8 + mg) * 3 + limb) * 32 + lane];
                afr[limb][0] = v.x; afr[limb][1] = v.y;
                afr[limb][2] = v.z; afr[limb][3] = v.w;
            }
            uint32_t bfr[3][4][2];
            #pragma unroll
            for (int limb = 0; limb < 3; limb++)
                #pragma unroll
                for (int hf = 0; hf < 2; hf++) {
                    uint4 v = Bb[((s * 3 + limb) * 4 + ng * 2 + hf) * 32 + lane];
                    bfr[limb][hf * 2    ][0] = v.x; bfr[limb][hf * 2    ][1] = v.y;
                    bfr[limb][hf * 2 + 1][0] = v.z; bfr[limb][hf * 2 + 1][1] = v.w;
                }
            #pragma unroll
            for (int term = 0; term < 6; term++) {
                const int la = TLA[term], lb = TLB[term];
                #pragma unroll
                for (int nt = 0; nt < 4; nt++)
                    mma_bf16(acc[nt], afr[la], bfr[lb][nt]);
            }
        }

        // ---- epilogue: d2 = ||c||^2 - 2*dot, strict-< running min (n ascending)
        #pragma unroll
        for (int nt = 0; nt < 4; nt++) {
            int nl = c * 64 + ng * 32 + nt * 8 + 2 * (lane & 3);
            float cv0 = cn[nl], cv1 = cn[nl + 1];
            int n = kb0 + nl;
            float d00 = fmaf(-2.f, acc[nt][0], cv0);   // row lane>>2
            float d01 = fmaf(-2.f, acc[nt][1], cv1);
            float d10 = fmaf(-2.f, acc[nt][2], cv0);   // row (lane>>2)+8
            float d11 = fmaf(-2.f, acc[nt][3], cv1);
            if (d00 < minv[0]) { minv[0] = d00; mini[0] = n; }
            if (d01 < minv[0]) { minv[0] = d01; mini[0] = n + 1; }
            if (d10 < minv[1]) { minv[1] = d10; mini[1] = n; }
            if (d11 < minv[1]) { minv[1] = d11; mini[1] = n + 1; }
        }
        __syncthreads();
    }

    // ---- cross-thread reduce: 8 candidates per token -> g_cv/g_ci[half]
    float* rv = reinterpret_cast<float*>(smem4);          // [128][8]
    int*   ri = reinterpret_cast<int*>(rv + 1024);
    #pragma unroll
    for (int rh = 0; rh < 2; rh++) {
        int tok  = mg * 16 + rh * 8 + (lane >> 2);
        int slot = ng * 4 + (lane & 3);
        rv[tok * 8 + slot] = minv[rh];
        ri[tok * 8 + slot] = mini[rh];
    }
    __syncthreads();
    if (tid < 128) {
        float bv = rv[tid * 8];
        int   bi = ri[tid * 8];
        #pragma unroll
        for (int x = 1; x < 8; x++) {
            float v = rv[tid * 8 + x];
            int   k = ri[tid * 8 + x];
            if (v < bv || (v == bv && k < bi)) { bv = v; bi = k; }
        }
        g_cv[half * N_TOK + n0 + tid] = bv;
        g_ci[half * N_TOK + n0 + tid] = bi;
    }
}

// ---------------------------------------------------------------------------
// Kernel 3: gather + split-K merge. Warp = 32 consecutive t, 8-wide d slice.
// half0 indices < half1, so half0 wins ties (first-min semantics).
// ---------------------------------------------------------------------------
__global__ void vq_gather_kernel(const float* __restrict__ cb, float* __restrict__ out) {
    int gw   = (blockIdx.x * blockDim.x + threadIdx.x) >> 5;   // 32768 warps
    int lane = threadIdx.x & 31;
    int t  = ((gw & 127) << 5) + lane;
    int d0 = ((gw >> 7) & 15) << 3;
    int b  = gw >> 11;
    int tg = b * T_DIM + t;
    float v0 = g_cv[tg], v1 = g_cv[N_TOK + tg];
    int idx = (v1 < v0) ? g_ci[N_TOK + tg] : g_ci[tg];
    const float4* src = reinterpret_cast<const float4*>(cb + (size_t)idx * D_DIM + d0);
    float4 w0 = __ldg(src);
    float4 w1 = __ldg(src + 1);
    size_t obase = ((size_t)b * D_DIM + d0) * T_DIM + t;
    out[obase + 0 * T_DIM] = w0.x;
    out[obase + 1 * T_DIM] = w0.y;
    out[obase + 2 * T_DIM] = w0.z;
    out[obase + 3 * T_DIM] = w0.w;
    out[obase + 4 * T_DIM] = w1.x;
    out[obase + 5 * T_DIM] = w1.y;
    out[obase + 6 * T_DIM] = w1.z;
    out[obase + 7 * T_DIM] = w1.w;
}

// ---------------------------------------------------------------------------
extern "C" void kernel_launch(void* const* d_in, const int* in_sizes, int n_in,
                              void* d_out, int out_size) {
    const float* z  = (const float*)d_in[0];
    const float* cb = (const float*)d_in[1];
    float* out = (float*)d_out;

    cudaFuncSetAttribute(vq_argmin_kernel,
                         cudaFuncAttributeMaxDynamicSharedMemorySize, SMEM_BYTES);

    vq_cnorm_kernel<<<K_DIM / 8, 256>>>(cb);
    vq_bfrag_kernel<<<768, 256>>>(cb);
    vq_argmin_kernel<<<(N_TOK / 128) * 2, 512, SMEM_BYTES>>>(z);
    vq_gather_kernel<<<4096, 256>>>(cb, out);
}

// round 9
// speedup vs baseline: 3.8897x; 1.5984x over previous
#include <cuda_runtime.h>
#include <cuda_fp16.h>
#include <cstdint>

// VectorQuantizerRestart: z [16,128,4096] fp32, codebook [1024,128] fp32
#define D_DIM 128
#define T_DIM 4096
#define K_DIM 1024
#define N_TOK 65536

__device__ float g_cnorm[K_DIM];
// split-K candidates: [half 2][token]
__device__ float g_cv[2 * N_TOK];
__device__ int   g_ci[2 * N_TOK];
// fp16 2-limb codebook, fragment-ordered: [c16][s8][limb2][ntp4][lane32][q4] uint32(f16x2)
__device__ __align__(16) uint32_t g_bfrag[16 * 8 * 2 * 4 * 32 * 4];

__device__ __forceinline__ void split2(float x, unsigned short& h, unsigned short& m) {
    __half hh = __float2half_rn(x);
    float r = x - __half2float(hh);
    __half mm = __float2half_rn(r);
    h = __half_as_ushort(hh);
    m = __half_as_ushort(mm);
}

__device__ __forceinline__ void mma_f16(float* d, const uint32_t* a, const uint32_t* b) {
    asm volatile(
        "mma.sync.aligned.m16n8k16.row.col.f32.f16.f16.f32 "
        "{%0,%1,%2,%3}, {%4,%5,%6,%7}, {%8,%9}, {%0,%1,%2,%3};"
        : "+f"(d[0]), "+f"(d[1]), "+f"(d[2]), "+f"(d[3])
        : "r"(a[0]), "r"(a[1]), "r"(a[2]), "r"(a[3]), "r"(b[0]), "r"(b[1]));
}

// ---------------------------------------------------------------------------
// Kernel 1: codebook squared norms (one warp per code).
// ---------------------------------------------------------------------------
__global__ void vq_cnorm_kernel(const float* __restrict__ cb) {
    int w    = (blockIdx.x * blockDim.x + threadIdx.x) >> 5;
    int lane = threadIdx.x & 31;
    if (w >= K_DIM) return;
    float s = 0.f;
    #pragma unroll
    for (int d = lane; d < D_DIM; d += 32) {
        float v = cb[(size_t)w * D_DIM + d];
        s = fmaf(v, v, s);
    }
    #pragma unroll
    for (int o = 16; o > 0; o >>= 1) s += __shfl_xor_sync(0xffffffffu, s, o);
    if (lane == 0) g_cnorm[w] = s;
}

// ---------------------------------------------------------------------------
// Kernel 1b: split codebook into 2 fp16 limbs, fragment order for m16n8k16.
// b0: k=(lane&3)*2+{0,1}, b1: k+8; n = ntile*8 + (lane>>2).
// e = [c][s][limb][ntp][lane][q]: q>>1 = ntile within pair, q&1 = reg (k+8).
// ---------------------------------------------------------------------------
__global__ void vq_bfrag_kernel(const float* __restrict__ cb) {
    int e = blockIdx.x * blockDim.x + threadIdx.x;     // 131072
    int q    = e & 3;
    int lane = (e >> 2) & 31;
    int ntp  = (e >> 7) & 3;
    int limb = (e >> 9) & 1;
    int s    = (e >> 10) & 7;
    int c    = e >> 13;

    int n = c * 64 + (ntp * 2 + (q >> 1)) * 8 + (lane >> 2);
    int k = s * 16 + ((q & 1) << 3) + (lane & 3) * 2;
    float x0 = cb[n * D_DIM + k];
    float x1 = cb[n * D_DIM + k + 1];
    unsigned short h0, m0, h1, m1;
    split2(x0, h0, m0);
    split2(x1, h1, m1);
    unsigned short lo = (limb == 0) ? h0 : m0;
    unsigned short hi = (limb == 0) ? h1 : m1;
    g_bfrag[e] = (uint32_t)lo | ((uint32_t)hi << 16);
}

// ---------------------------------------------------------------------------
// Kernel 2: 3-term fp16 2-limb mma.sync + register argmin, split-K over codes.
// grid = 1024: blockIdx = tile*2 + half; each CTA covers 512 codes (8 chunks).
// CTA: 512 thr = 16 warps = 8 mg x 2 ng (4 warps/SMSP); warp tile m16n32.
// A (64KB, 2 limbs) resident; B double-buffered (2 x 32KB), cp.async 1 ahead.
// fp16 2-limb 3-term == 3xTF32 error structure (~2^-22 rel) which passed
// with rel_err 0.0 in R4/R5.
// ---------------------------------------------------------------------------
#define A_U4   4096            // uint4: [s8][mt8][limb2][lane32]
#define B_U4   2048            // per buffer: [s8][limb2][ntp4][lane32]
#define SMEM_BYTES ((A_U4 + 2 * B_U4) * 16 + 512 * 4)   // 133120

__global__ __launch_bounds__(512, 1)
void vq_argmin_kernel(const float* __restrict__ z) {
    extern __shared__ uint4 smem4[];
    uint4* As = smem4;
    uint4* Bs = smem4 + A_U4;
    float* cn = reinterpret_cast<float*>(smem4 + A_U4 + 2 * B_U4);

    const int tid  = threadIdx.x;
    const int lane = tid & 31;
    const int w    = tid >> 5;
    const int mg   = w >> 1;                 // 0..7  (m16 tile)
    const int ng   = w & 1;                  // 0..1  (n32 tile)

    const int tile = blockIdx.x >> 1;
    const int half = blockIdx.x & 1;
    const int n0 = tile * 128;
    const int kb0 = half * 512;
    const int bb = n0 >> 12;
    const int t0 = n0 & (T_DIM - 1);
    const float* zb = z + (size_t)bb * D_DIM * T_DIM + t0;

    cn[tid] = g_cnorm[kb0 + tid];

    // ---- A prologue: z -> 2 fp16 limbs in m16n8k16 fragment order.
    for (int p = w; p < 64; p += 16) {
        int s  = p >> 3;
        int mt = p & 7;
        int m = mt * 16 + (lane >> 2);
        int k = s * 16 + (lane & 3) * 2;
        float xv[8];
        xv[0] = zb[(k    ) * T_DIM + m    ];  xv[1] = zb[(k + 1) * T_DIM + m    ];
        xv[2] = zb[(k    ) * T_DIM + m + 8];  xv[3] = zb[(k + 1) * T_DIM + m + 8];
        xv[4] = zb[(k + 8) * T_DIM + m    ];  xv[5] = zb[(k + 9) * T_DIM + m    ];
        xv[6] = zb[(k + 8) * T_DIM + m + 8];  xv[7] = zb[(k + 9) * T_DIM + m + 8];
        unsigned short hh[8], mm[8];
        #pragma unroll
        for (int i = 0; i < 8; i++) split2(xv[i], hh[i], mm[i]);
        #pragma unroll
        for (int limb = 0; limb < 2; limb++) {
            const unsigned short* u = (limb == 0) ? hh : mm;
            uint4 v;
            v.x = (uint32_t)u[0] | ((uint32_t)u[1] << 16);
            v.y = (uint32_t)u[2] | ((uint32_t)u[3] << 16);
            v.z = (uint32_t)u[4] | ((uint32_t)u[5] << 16);
            v.w = (uint32_t)u[6] | ((uint32_t)u[7] << 16);
            As[((s * 8 + mt) * 2 + limb) * 32 + lane] = v;
        }
    }

    float minv[2];
    int   mini[2];
    minv[0] = minv[1] = 3.4e38f;
    mini[0] = mini[1] = 0;

    const uint32_t bsm = (uint32_t)__cvta_generic_to_shared(Bs);
    const float4*  bsrc = reinterpret_cast<const float4*>(g_bfrag) + half * 8 * B_U4;

    // prefetch local chunk 0 into buffer 0 (2048 u4 / 512 thr = 4 each)
    #pragma unroll
    for (int i = 0; i < 4; ++i) {
        int e = i * 512 + tid;
        asm volatile("cp.async.cg.shared.global [%0], [%1], 16;"
                     :: "r"(bsm + (uint32_t)e * 16u), "l"(bsrc + e) : "memory");
    }
    asm volatile("cp.async.commit_group;" ::: "memory");

    static const int TLA[3] = {0, 0, 1};
    static const int TLB[3] = {0, 1, 0};

    #pragma unroll 1
    for (int c = 0; c < 8; ++c) {
        if (c < 7) {
            int buf1 = (c + 1) & 1;
            const float4* src = bsrc + (c + 1) * B_U4;
            #pragma unroll
            for (int i = 0; i < 4; ++i) {
                int e = i * 512 + tid;
                asm volatile("cp.async.cg.shared.global [%0], [%1], 16;"
                             :: "r"(bsm + (uint32_t)(buf1 * B_U4 + e) * 16u),
                                "l"(src + e) : "memory");
            }
            asm volatile("cp.async.commit_group;" ::: "memory");
            asm volatile("cp.async.wait_group 1;" ::: "memory");
        } else {
            asm volatile("cp.async.wait_group 0;" ::: "memory");
        }
        __syncthreads();

        const uint4* Bb = Bs + (c & 1) * B_U4;
        float acc[4][4];
        #pragma unroll
        for (int nt = 0; nt < 4; nt++)
            #pragma unroll
            for (int qi = 0; qi < 4; qi++) acc[nt][qi] = 0.f;

        #pragma unroll
        for (int s = 0; s < 8; ++s) {
            uint32_t afr[2][4];
            #pragma unroll
            for (int limb = 0; limb < 2; limb++) {
                uint4 v = As[((s * 8 + mg) * 2 + limb) * 32 + lane];
                afr[limb][0] = v.x; afr[limb][1] = v.y;
                afr[limb][2] = v.z; afr[limb][3] = v.w;
            }
            uint32_t bfr[2][4][2];
            #pragma unroll
            for (int limb = 0; limb < 2; limb++)
                #pragma unroll
                for (int hf = 0; hf < 2; hf++) {
                    uint4 v = Bb[((s * 2 + limb) * 4 + ng * 2 + hf) * 32 + lane];
                    bfr[limb][hf * 2    ][0] = v.x; bfr[limb][hf * 2    ][1] = v.y;
                    bfr[limb][hf * 2 + 1][0] = v.z; bfr[limb][hf * 2 + 1][1] = v.w;
                }
            // 3 terms: h*h, h*m, m*h (m*m ~ 2^-22 rel: negligible, matches 3xTF32)
            #pragma unroll
            for (int term = 0; term < 3; term++) {
                const int la = TLA[term], lb = TLB[term];
                #pragma unroll
                for (int nt = 0; nt < 4; nt++)
                    mma_f16(acc[nt], afr[la], bfr[lb][nt]);
            }
        }

        // ---- epilogue: d2 = ||c||^2 - 2*dot, strict-< running min (n ascending)
        #pragma unroll
        for (int nt = 0; nt < 4; nt++) {
            int nl = c * 64 + ng * 32 + nt * 8 + 2 * (lane & 3);
            float cv0 = cn[nl], cv1 = cn[nl + 1];
            int n = kb0 + nl;
            float d00 = fmaf(-2.f, acc[nt][0], cv0);
            float d01 = fmaf(-2.f, acc[nt][1], cv1);
            float d10 = fmaf(-2.f, acc[nt][2], cv0);
            float d11 = fmaf(-2.f, acc[nt][3], cv1);
            if (d00 < minv[0]) { minv[0] = d00; mini[0] = n; }
            if (d01 < minv[0]) { minv[0] = d01; mini[0] = n + 1; }
            if (d10 < minv[1]) { minv[1] = d10; mini[1] = n; }
            if (d11 < minv[1]) { minv[1] = d11; mini[1] = n + 1; }
        }
        __syncthreads();
    }

    // ---- cross-thread reduce: 8 candidates per token -> g_cv/g_ci[half]
    float* rv = reinterpret_cast<float*>(smem4);          // [128][8]
    int*   ri = reinterpret_cast<int*>(rv + 1024);
    #pragma unroll
    for (int rh = 0; rh < 2; rh++) {
        int tok  = mg * 16 + rh * 8 + (lane >> 2);
        int slot = ng * 4 + (lane & 3);
        rv[tok * 8 + slot] = minv[rh];
        ri[tok * 8 + slot] = mini[rh];
    }
    __syncthreads();
    if (tid < 128) {
        float bv = rv[tid * 8];
        int   bi = ri[tid * 8];
        #pragma unroll
        for (int x = 1; x < 8; x++) {
            float v = rv[tid * 8 + x];
            int   k = ri[tid * 8 + x];
            if (v < bv || (v == bv && k < bi)) { bv = v; bi = k; }
        }
        g_cv[half * N_TOK + n0 + tid] = bv;
        g_ci[half * N_TOK + n0 + tid] = bi;
    }
}

// ---------------------------------------------------------------------------
// Kernel 3: gather + split-K merge. Warp = 32 consecutive t, 8-wide d slice.
// half0 indices < half1, so half0 wins ties (first-min semantics).
// ---------------------------------------------------------------------------
__global__ void vq_gather_kernel(const float* __restrict__ cb, float* __restrict__ out) {
    int gw   = (blockIdx.x * blockDim.x + threadIdx.x) >> 5;   // 32768 warps
    int lane = threadIdx.x & 31;
    int t  = ((gw & 127) << 5) + lane;
    int d0 = ((gw >> 7) & 15) << 3;
    int b  = gw >> 11;
    int tg = b * T_DIM + t;
    float v0 = g_cv[tg], v1 = g_cv[N_TOK + tg];
    int idx = (v1 < v0) ? g_ci[N_TOK + tg] : g_ci[tg];
    const float4* src = reinterpret_cast<const float4*>(cb + (size_t)idx * D_DIM + d0);
    float4 w0 = __ldg(src);
    float4 w1 = __ldg(src + 1);
    size_t obase = ((size_t)b * D_DIM + d0) * T_DIM + t;
    out[obase + 0 * T_DIM] = w0.x;
    out[obase + 1 * T_DIM] = w0.y;
    out[obase + 2 * T_DIM] = w0.z;
    out[obase + 3 * T_DIM] = w0.w;
    out[obase + 4 * T_DIM] = w1.x;
    out[obase + 5 * T_DIM] = w1.y;
    out[obase + 6 * T_DIM] = w1.z;
    out[obase + 7 * T_DIM] = w1.w;
}

// ---------------------------------------------------------------------------
extern "C" void kernel_launch(void* const* d_in, const int* in_sizes, int n_in,
                              void* d_out, int out_size) {
    const float* z  = (const float*)d_in[0];
    const float* cb = (const float*)d_in[1];
    float* out = (float*)d_out;

    cudaFuncSetAttribute(vq_argmin_kernel,
                         cudaFuncAttributeMaxDynamicSharedMemorySize, SMEM_BYTES);

    vq_cnorm_kernel<<<K_DIM / 8, 256>>>(cb);
    vq_bfrag_kernel<<<512, 256>>>(cb);
    vq_argmin_kernel<<<(N_TOK / 128) * 2, 512, SMEM_BYTES>>>(z);
    vq_gather_kernel<<<4096, 256>>>(cb, out);
}

// round 10
// speedup vs baseline: 4.0729x; 1.0471x over previous
#include <cuda_runtime.h>
#include <cuda_fp16.h>
#include <cstdint>

// VectorQuantizerRestart: z [16,128,4096] fp32, codebook [1024,128] fp32
#define D_DIM 128
#define T_DIM 4096
#define K_DIM 1024
#define N_TOK 65536

__device__ __align__(16) float g_cnorm[K_DIM];
// split-K candidates: [half 2][token]
__device__ float g_cv[2 * N_TOK];
__device__ int   g_ci[2 * N_TOK];
// fp16 2-limb codebook, fragment-ordered:
// [half2][chunk4][s8][limb2][ntp8][lane32][q4] uint32(f16x2)  (512 KB)
__device__ __align__(16) uint32_t g_bfrag[2 * 4 * 8 * 2 * 8 * 32 * 4];

__device__ __forceinline__ void split2(float x, unsigned short& h, unsigned short& m) {
    __half hh = __float2half_rn(x);
    float r = x - __half2float(hh);
    __half mm = __float2half_rn(r);
    h = __half_as_ushort(hh);
    m = __half_as_ushort(mm);
}

__device__ __forceinline__ void mma_f16(float* d, const uint32_t* a, const uint32_t* b) {
    asm volatile(
        "mma.sync.aligned.m16n8k16.row.col.f32.f16.f16.f32 "
        "{%0,%1,%2,%3}, {%4,%5,%6,%7}, {%8,%9}, {%0,%1,%2,%3};"
        : "+f"(d[0]), "+f"(d[1]), "+f"(d[2]), "+f"(d[3])
        : "r"(a[0]), "r"(a[1]), "r"(a[2]), "r"(a[3]), "r"(b[0]), "r"(b[1]));
}

// ---------------------------------------------------------------------------
// Kernel 1: codebook squared norms (one warp per code).
// ---------------------------------------------------------------------------
__global__ void vq_cnorm_kernel(const float* __restrict__ cb) {
    int w    = (blockIdx.x * blockDim.x + threadIdx.x) >> 5;
    int lane = threadIdx.x & 31;
    if (w >= K_DIM) return;
    float s = 0.f;
    #pragma unroll
    for (int d = lane; d < D_DIM; d += 32) {
        float v = cb[(size_t)w * D_DIM + d];
        s = fmaf(v, v, s);
    }
    #pragma unroll
    for (int o = 16; o > 0; o >>= 1) s += __shfl_xor_sync(0xffffffffu, s, o);
    if (lane == 0) g_cnorm[w] = s;
}

// ---------------------------------------------------------------------------
// Kernel 1b: split codebook into 2 fp16 limbs, fragment order for m16n8k16.
// e = [half][chunk][s][limb][ntp][lane][q]
// n = half*512 + chunk*128 + (ntp*2 + (q>>1))*8 + (lane>>2)
// k = s*16 + ((q&1)<<3) + (lane&3)*2
// ---------------------------------------------------------------------------
__global__ void vq_bfrag_kernel(const float* __restrict__ cb) {
    int e = blockIdx.x * blockDim.x + threadIdx.x;     // 131072
    int q    = e & 3;
    int lane = (e >> 2) & 31;
    int ntp  = (e >> 7) & 7;
    int limb = (e >> 10) & 1;
    int s    = (e >> 11) & 7;
    int chunk= (e >> 14) & 3;
    int half = (e >> 16) & 1;

    int n = half * 512 + chunk * 128 + (ntp * 2 + (q >> 1)) * 8 + (lane >> 2);
    int k = s * 16 + ((q & 1) << 3) + (lane & 3) * 2;
    float x0 = cb[n * D_DIM + k];
    float x1 = cb[n * D_DIM + k + 1];
    unsigned short h0, m0, h1, m1;
    split2(x0, h0, m0);
    split2(x1, h1, m1);
    unsigned short lo = (limb == 0) ? h0 : m0;
    unsigned short hi = (limb == 0) ? h1 : m1;
    g_bfrag[e] = (uint32_t)lo | ((uint32_t)hi << 16);
}

// ---------------------------------------------------------------------------
// Kernel 2: 3-term fp16 2-limb mma.sync + register argmin, split-K over codes.
// grid = 1024: blockIdx = tile*2 + half; each CTA = 512 codes in 4 chunks of 128.
// CTA: 512 thr = 16 warps = 8 mg x 2 ng; warp tile m16 x n64.
// A (64KB) resident; B double-buffered (2 x 64KB), single-sync pipeline.
// ---------------------------------------------------------------------------
#define A_U4   4096            // uint4: [s8][mt8][limb2][lane32]
#define B_U4   4096            // per buffer: [s8][limb2][ntp8][lane32]
#define SMEM_BYTES ((A_U4 + 2 * B_U4) * 16 + 512 * 4)   // 198656

__global__ __launch_bounds__(512, 1)
void vq_argmin_kernel(const float* __restrict__ z) {
    extern __shared__ uint4 smem4[];
    uint4* As = smem4;
    uint4* Bs = smem4 + A_U4;
    float* cn = reinterpret_cast<float*>(smem4 + A_U4 + 2 * B_U4);

    const int tid  = threadIdx.x;
    const int lane = tid & 31;
    const int w    = tid >> 5;
    const int mg   = w >> 1;                 // 0..7  (m16 tile)
    const int ng   = w & 1;                  // 0..1  (n64 tile)

    const int tile = blockIdx.x >> 1;
    const int half = blockIdx.x & 1;
    const int n0 = tile * 128;
    const int kb0 = half * 512;
    const int bb = n0 >> 12;
    const int t0 = n0 & (T_DIM - 1);
    const float* zb = z + (size_t)bb * D_DIM * T_DIM + t0;

    const uint32_t bsm = (uint32_t)__cvta_generic_to_shared(Bs);
    const uint32_t cnsm = (uint32_t)__cvta_generic_to_shared(cn);
    const float4*  bsrc = reinterpret_cast<const float4*>(g_bfrag) + half * 4 * B_U4;

    // ---- group 0: cn (2KB) + B chunk 0 (64KB) — overlaps the A-split below
    if (tid < 128) {
        asm volatile("cp.async.ca.shared.global [%0], [%1], 16;"
                     :: "r"(cnsm + tid * 16u), "l"(g_cnorm + kb0 + tid * 4) : "memory");
    }
    #pragma unroll
    for (int i = 0; i < 8; ++i) {
        int e = i * 512 + tid;
        asm volatile("cp.async.cg.shared.global [%0], [%1], 16;"
                     :: "r"(bsm + (uint32_t)e * 16u), "l"(bsrc + e) : "memory");
    }
    asm volatile("cp.async.commit_group;" ::: "memory");

    // ---- A prologue: z -> 2 fp16 limbs in m16n8k16 fragment order.
    for (int p = w; p < 64; p += 16) {
        int s  = p >> 3;
        int mt = p & 7;
        int m = mt * 16 + (lane >> 2);
        int k = s * 16 + (lane & 3) * 2;
        float xv[8];
        xv[0] = zb[(k    ) * T_DIM + m    ];  xv[1] = zb[(k + 1) * T_DIM + m    ];
        xv[2] = zb[(k    ) * T_DIM + m + 8];  xv[3] = zb[(k + 1) * T_DIM + m + 8];
        xv[4] = zb[(k + 8) * T_DIM + m    ];  xv[5] = zb[(k + 9) * T_DIM + m    ];
        xv[6] = zb[(k + 8) * T_DIM + m + 8];  xv[7] = zb[(k + 9) * T_DIM + m + 8];
        unsigned short hh[8], mm[8];
        #pragma unroll
        for (int i = 0; i < 8; i++) split2(xv[i], hh[i], mm[i]);
        #pragma unroll
        for (int limb = 0; limb < 2; limb++) {
            const unsigned short* u = (limb == 0) ? hh : mm;
            uint4 v;
            v.x = (uint32_t)u[0] | ((uint32_t)u[1] << 16);
            v.y = (uint32_t)u[2] | ((uint32_t)u[3] << 16);
            v.z = (uint32_t)u[4] | ((uint32_t)u[5] << 16);
            v.w = (uint32_t)u[6] | ((uint32_t)u[7] << 16);
            As[((s * 8 + mt) * 2 + limb) * 32 + lane] = v;
        }
    }

    float minv[2];
    int   mini[2];
    minv[0] = minv[1] = 3.4e38f;
    mini[0] = mini[1] = 0;

    static const int TLA[3] = {0, 0, 1};
    static const int TLB[3] = {0, 1, 0};

    #pragma unroll 1
    for (int c = 0; c < 4; ++c) {
        asm volatile("cp.async.wait_group 0;" ::: "memory");
        __syncthreads();     // buf[c&1]+A(+cn) visible; all done reading buf[(c+1)&1]

        if (c < 3) {         // prefetch c+1 into the buffer just freed
            int buf1 = (c + 1) & 1;
            const float4* src = bsrc + (c + 1) * B_U4;
            #pragma unroll
            for (int i = 0; i < 8; ++i) {
                int e = i * 512 + tid;
                asm volatile("cp.async.cg.shared.global [%0], [%1], 16;"
                             :: "r"(bsm + (uint32_t)(buf1 * B_U4 + e) * 16u),
                                "l"(src + e) : "memory");
            }
            asm volatile("cp.async.commit_group;" ::: "memory");
        }

        const uint4* Bb = Bs + (c & 1) * B_U4;
        float acc[8][4];
        #pragma unroll
        for (int nt = 0; nt < 8; nt++)
            #pragma unroll
            for (int qi = 0; qi < 4; qi++) acc[nt][qi] = 0.f;

        #pragma unroll
        for (int s = 0; s < 8; ++s) {
            uint32_t afr[2][4];
            #pragma unroll
            for (int limb = 0; limb < 2; limb++) {
                uint4 v = As[((s * 8 + mg) * 2 + limb) * 32 + lane];
                afr[limb][0] = v.x; afr[limb][1] = v.y;
                afr[limb][2] = v.z; afr[limb][3] = v.w;
            }
            uint32_t bfr[2][8][2];            // [limb][ntile][2 regs]
            #pragma unroll
            for (int limb = 0; limb < 2; limb++)
                #pragma unroll
                for (int np = 0; np < 4; np++) {
                    uint4 v = Bb[((s * 2 + limb) * 8 + ng * 4 + np) * 32 + lane];
                    bfr[limb][np * 2    ][0] = v.x; bfr[limb][np * 2    ][1] = v.y;
                    bfr[limb][np * 2 + 1][0] = v.z; bfr[limb][np * 2 + 1][1] = v.w;
                }
            // 3 terms: h*h, h*m, m*h (m*m ~ 2^-22 rel: negligible)
            #pragma unroll
            for (int term = 0; term < 3; term++) {
                const int la = TLA[term], lb = TLB[term];
                #pragma unroll
                for (int nt = 0; nt < 8; nt++)
                    mma_f16(acc[nt], afr[la], bfr[lb][nt]);
            }
        }

        // ---- epilogue: d2 = ||c||^2 - 2*dot, strict-< running min (n ascending)
        #pragma unroll
        for (int nt = 0; nt < 8; nt++) {
            int nl = c * 128 + ng * 64 + nt * 8 + 2 * (lane & 3);
            float cv0 = cn[nl], cv1 = cn[nl + 1];
            int n = kb0 + nl;
            float d00 = fmaf(-2.f, acc[nt][0], cv0);
            float d01 = fmaf(-2.f, acc[nt][1], cv1);
            float d10 = fmaf(-2.f, acc[nt][2], cv0);
            float d11 = fmaf(-2.f, acc[nt][3], cv1);
            if (d00 < minv[0]) { minv[0] = d00; mini[0] = n; }
            if (d01 < minv[0]) { minv[0] = d01; mini[0] = n + 1; }
            if (d10 < minv[1]) { minv[1] = d10; mini[1] = n; }
            if (d11 < minv[1]) { minv[1] = d11; mini[1] = n + 1; }
        }
    }

    // ---- cross-thread reduce: 8 candidates per token -> g_cv/g_ci[half]
    __syncthreads();                          // all compute done before smem reuse
    float* rv = reinterpret_cast<float*>(smem4);          // [128][8]
    int*   ri = reinterpret_cast<int*>(rv + 1024);
    #pragma unroll
    for (int rh = 0; rh < 2; rh++) {
        int tok  = mg * 16 + rh * 8 + (lane >> 2);
        int slot = ng * 4 + (lane & 3);
        rv[tok * 8 + slot] = minv[rh];
        ri[tok * 8 + slot] = mini[rh];
    }
    __syncthreads();
    if (tid < 128) {
        float bv = rv[tid * 8];
        int   bi = ri[tid * 8];
        #pragma unroll
        for (int x = 1; x < 8; x++) {
            float v = rv[tid * 8 + x];
            int   k = ri[tid * 8 + x];
            if (v < bv || (v == bv && k < bi)) { bv = v; bi = k; }
        }
        g_cv[half * N_TOK + n0 + tid] = bv;
        g_ci[half * N_TOK + n0 + tid] = bi;
    }
}

// ---------------------------------------------------------------------------
// Kernel 3: gather + split-K merge. Warp = 32 consecutive t, 8-wide d slice.
// half0 indices < half1, so half0 wins ties (first-min semantics).
// ---------------------------------------------------------------------------
__global__ void vq_gather_kernel(const float* __restrict__ cb, float* __restrict__ out) {
    int gw   = (blockIdx.x * blockDim.x + threadIdx.x) >> 5;   // 32768 warps
    int lane = threadIdx.x & 31;
    int t  = ((gw & 127) << 5) + lane;
    int d0 = ((gw >> 7) & 15) << 3;
    int b  = gw >> 11;
    int tg = b * T_DIM + t;
    float v0 = g_cv[tg], v1 = g_cv[N_TOK + tg];
    int idx = (v1 < v0) ? g_ci[N_TOK + tg] : g_ci[tg];
    const float4* src = reinterpret_cast<const float4*>(cb + (size_t)idx * D_DIM + d0);
    float4 w0 = __ldg(src);
    float4 w1 = __ldg(src + 1);
    size_t obase = ((size_t)b * D_DIM + d0) * T_DIM + t;
    out[obase + 0 * T_DIM] = w0.x;
    out[obase + 1 * T_DIM] = w0.y;
    out[obase + 2 * T_DIM] = w0.z;
    out[obase + 3 * T_DIM] = w0.w;
    out[obase + 4 * T_DIM] = w1.x;
    out[obase + 5 * T_DIM] = w1.y;
    out[obase + 6 * T_DIM] = w1.z;
    out[obase + 7 * T_DIM] = w1.w;
}

// ---------------------------------------------------------------------------
extern "C" void kernel_launch(void* const* d_in, const int* in_sizes, int n_in,
                              void* d_out, int out_size) {
    const float* z  = (const float*)d_in[0];
    const float* cb = (const float*)d_in[1];
    float* out = (float*)d_out;

    cudaFuncSetAttribute(vq_argmin_kernel,
                         cudaFuncAttributeMaxDynamicSharedMemorySize, SMEM_BYTES);

    vq_cnorm_kernel<<<K_DIM / 8, 256>>>(cb);
    vq_bfrag_kernel<<<512, 256>>>(cb);
    vq_argmin_kernel<<<(N_TOK / 128) * 2, 512, SMEM_BYTES>>>(z);
    vq_gather_kernel<<<4096, 256>>>(cb, out);
}